// round 1
// baseline (speedup 1.0000x reference)
#include <cuda_runtime.h>
#include <cstdint>

#define CDIM   128
#define NNODES 100000
#define NEDGES 200000

typedef unsigned long long ull;

// Scratch (static __device__ arrays: allocation-free).
// A: GEMM outputs (max 200k rows), B: nodes_l1, C: edges_l1, D: level-2 accumulator.
__device__ __align__(128) float g_bufA[(size_t)NEDGES * CDIM];
__device__ __align__(128) float g_bufB[(size_t)NNODES * CDIM];
__device__ __align__(128) float g_bufC[(size_t)NEDGES * CDIM];
__device__ __align__(128) float g_bufD[(size_t)NNODES * CDIM];

// ---------------- packed f32x2 helpers (FFMA2: 2x fp32 FMA throughput) ----------------
__device__ __forceinline__ ull fma2(ull a, ull b, ull c) {
    ull d;
    asm("fma.rn.f32x2 %0, %1, %2, %3;" : "=l"(d) : "l"(a), "l"(b), "l"(c));
    return d;
}
__device__ __forceinline__ ull dup2(float x) {
    ull d;
    asm("mov.b64 %0, {%1, %1};" : "=l"(d) : "f"(x));
    return d;
}
__device__ __forceinline__ float2 unpack2(ull v) {
    float2 r;
    asm("mov.b64 {%0, %1}, %2;" : "=f"(r.x), "=f"(r.y) : "l"(v));
    return r;
}

// ---------------- GEMM: out[M,128] = A[M,128] @ W[128,128] (fp32) ----------------
// Block: 256 threads, tile 128 rows x 128 cols, 8x8 per-thread register tile.
// Whole K=128 staged in smem. A stored transposed with XOR-chunk swizzle:
//   element (k, r) at  k*128 + ((r>>2) ^ (k>>2))*4 + (r&3)
// -> compute reads are aligned 16B, conflict-free; transpose store is 4-way only.
__global__ __launch_bounds__(256, 1) void gemm128(const float* __restrict__ A,
                                                  const float* __restrict__ W,
                                                  float* __restrict__ out, int M)
{
    extern __shared__ float smem[];
    float* sA = smem;            // 16384 floats (64 KB), swizzled transposed A tile
    float* sW = smem + 16384;    // 16384 floats (64 KB), W row-major [k][n]

    const int tid  = threadIdx.x;
    const int row0 = blockIdx.x * 128;

    // Stage W (coalesced float4)
    #pragma unroll
    for (int i = 0; i < 16; ++i) {
        int e = tid + i * 256;   // float4 index, 0..4095
        reinterpret_cast<float4*>(sW)[e] = reinterpret_cast<const float4*>(W)[e];
    }
    // Stage A transposed + swizzled
    #pragma unroll
    for (int i = 0; i < 16; ++i) {
        int e  = tid + i * 256;  // float4 index
        int r  = e >> 5;         // local row 0..127
        int kq = e & 31;         // float4 index along k
        float4 v = make_float4(0.f, 0.f, 0.f, 0.f);
        int grow = row0 + r;
        if (grow < M) v = reinterpret_cast<const float4*>(A)[(size_t)grow * 32 + kq];
        float vv[4] = {v.x, v.y, v.z, v.w};
        #pragma unroll
        for (int j = 0; j < 4; ++j) {
            int k = kq * 4 + j;
            int chunk = (r >> 2) ^ (k >> 2);
            sA[k * 128 + chunk * 4 + (r & 3)] = vv[j];
        }
    }
    __syncthreads();

    const int tx = tid & 15;
    const int ty = tid >> 4;
    const int cbase = tx * 8;    // 8 output cols
    const int c0 = ty * 2;       // chunk of rows ty*8..ty*8+3

    ull acc[4][8];               // [row-pair][col], each holds rows {2rp, 2rp+1}
    #pragma unroll
    for (int rp = 0; rp < 4; ++rp)
        #pragma unroll
        for (int c = 0; c < 8; ++c) acc[rp][c] = 0ull;

    #pragma unroll 8
    for (int k = 0; k < 128; ++k) {
        int s = k >> 2;
        ulonglong2 alo = *reinterpret_cast<const ulonglong2*>(&sA[k * 128 + ((c0 ^ s) << 2)]);
        ulonglong2 ahi = *reinterpret_cast<const ulonglong2*>(&sA[k * 128 + (((c0 + 1) ^ s) << 2)]);
        float4 w0 = *reinterpret_cast<const float4*>(&sW[k * 128 + cbase]);
        float4 w1 = *reinterpret_cast<const float4*>(&sW[k * 128 + cbase + 4]);
        ull wd[8] = {dup2(w0.x), dup2(w0.y), dup2(w0.z), dup2(w0.w),
                     dup2(w1.x), dup2(w1.y), dup2(w1.z), dup2(w1.w)};
        ull a2[4] = {alo.x, alo.y, ahi.x, ahi.y};
        #pragma unroll
        for (int rp = 0; rp < 4; ++rp)
            #pragma unroll
            for (int c = 0; c < 8; ++c)
                acc[rp][c] = fma2(a2[rp], wd[c], acc[rp][c]);
    }

    // Epilogue: rows row0 + ty*8 + 2*rp + {0,1}, cols cbase..cbase+7
    #pragma unroll
    for (int rp = 0; rp < 4; ++rp) {
        float2 f[8];
        #pragma unroll
        for (int c = 0; c < 8; ++c) f[c] = unpack2(acc[rp][c]);
        int grow = row0 + ty * 8 + rp * 2;
        if (grow < M) {
            float4 o0 = make_float4(f[0].x, f[1].x, f[2].x, f[3].x);
            float4 o1 = make_float4(f[4].x, f[5].x, f[6].x, f[7].x);
            *reinterpret_cast<float4*>(&out[(size_t)grow * 128 + cbase])     = o0;
            *reinterpret_cast<float4*>(&out[(size_t)grow * 128 + cbase + 4]) = o1;
        }
        if (grow + 1 < M) {
            float4 o0 = make_float4(f[0].y, f[1].y, f[2].y, f[3].y);
            float4 o1 = make_float4(f[4].y, f[5].y, f[6].y, f[7].y);
            *reinterpret_cast<float4*>(&out[(size_t)(grow + 1) * 128 + cbase])     = o0;
            *reinterpret_cast<float4*>(&out[(size_t)(grow + 1) * 128 + cbase + 4]) = o1;
        }
    }
}

// ---------------- COO SpMM: out[rows[e]] += vals[e] * X[cols[e]] ----------------
// Warp per nnz; each lane handles 4 channels; 16B vector reduction to L2.
__global__ __launch_bounds__(256) void spmm_atomic(const int* __restrict__ rows,
                                                   const int* __restrict__ cols,
                                                   const float* __restrict__ vals, int nnz,
                                                   const float* __restrict__ X,
                                                   float* __restrict__ out)
{
    int g    = blockIdx.x * blockDim.x + threadIdx.x;
    int e    = g >> 5;
    int lane = g & 31;
    if (e >= nnz) return;
    int   r = rows[e];
    int   c = cols[e];
    float v = vals[e];
    float4 xv = *reinterpret_cast<const float4*>(&X[(size_t)c * 128 + lane * 4]);
    float* dst = &out[(size_t)r * 128 + lane * 4];
    asm volatile("red.global.add.v4.f32 [%0], {%1, %2, %3, %4};"
                 :: "l"(dst), "f"(xv.x * v), "f"(xv.y * v), "f"(xv.z * v), "f"(xv.w * v)
                 : "memory");
}

// ---------------- elementwise ----------------
__global__ __launch_bounds__(256) void zero_kernel(float4* __restrict__ p, int n4)
{
    int i = blockIdx.x * blockDim.x + threadIdx.x;
    if (i < n4) p[i] = make_float4(0.f, 0.f, 0.f, 0.f);
}

__global__ __launch_bounds__(256) void sigmoid_kernel(const float4* __restrict__ in,
                                                      float4* __restrict__ out, int n4)
{
    int i = blockIdx.x * blockDim.x + threadIdx.x;
    if (i < n4) {
        float4 v = in[i];
        v.x = 1.f / (1.f + __expf(-v.x));
        v.y = 1.f / (1.f + __expf(-v.y));
        v.z = 1.f / (1.f + __expf(-v.z));
        v.w = 1.f / (1.f + __expf(-v.w));
        out[i] = v;
    }
}

// ---------------- launch ----------------
extern "C" void kernel_launch(void* const* d_in, const int* in_sizes, int n_in,
                              void* d_out, int out_size)
{
    const float* x        = (const float*)d_in[0];
    const float* W1_00    = (const float*)d_in[1];
    const float* W1_01    = (const float*)d_in[2];
    const float* W2_00    = (const float*)d_in[3];
    const float* W2_10    = (const float*)d_in[4];
    const int*   adj_rows = (const int*)  d_in[5];
    const int*   adj_cols = (const int*)  d_in[6];
    const float* adj_vals = (const float*)d_in[7];
    const int*   inc_rows = (const int*)  d_in[8];
    const int*   inc_cols = (const int*)  d_in[9];
    const float* inc_vals = (const float*)d_in[10];
    const int adj_nnz = in_sizes[5];
    const int inc_nnz = in_sizes[8];

    float *bufA, *bufB, *bufC, *bufD;
    cudaGetSymbolAddress((void**)&bufA, g_bufA);
    cudaGetSymbolAddress((void**)&bufB, g_bufB);
    cudaGetSymbolAddress((void**)&bufC, g_bufC);
    cudaGetSymbolAddress((void**)&bufD, g_bufD);

    cudaFuncSetAttribute(gemm128, cudaFuncAttributeMaxDynamicSharedMemorySize, 131072);

    const int NB4 = NNODES * CDIM / 4;   // 3,200,000 float4
    const int NE4 = NEDGES * CDIM / 4;   // 6,400,000 float4

    // 1) h1 = x @ W1_00 -> A
    gemm128<<<(NNODES + 127) / 128, 256, 131072>>>(x, W1_00, bufA, NNODES);
    // 2) nodes_l1 = sigmoid(adj @ h1) -> B
    zero_kernel<<<(NB4 + 255) / 256, 256>>>((float4*)bufB, NB4);
    spmm_atomic<<<(adj_nnz + 7) / 8, 256>>>(adj_rows, adj_cols, adj_vals, adj_nnz, bufA, bufB);
    sigmoid_kernel<<<(NB4 + 255) / 256, 256>>>((const float4*)bufB, (float4*)bufB, NB4);
    // 3) h2 = x @ W1_01 -> A
    gemm128<<<(NNODES + 127) / 128, 256, 131072>>>(x, W1_01, bufA, NNODES);
    // 4) edges_l1 = sigmoid(incT @ h2) -> C   (rows = inc_cols = edge ids)
    zero_kernel<<<(NE4 + 255) / 256, 256>>>((float4*)bufC, NE4);
    spmm_atomic<<<(inc_nnz + 7) / 8, 256>>>(inc_cols, inc_rows, inc_vals, inc_nnz, bufA, bufC);
    sigmoid_kernel<<<(NE4 + 255) / 256, 256>>>((const float4*)bufC, (float4*)bufC, NE4);
    // 5) h3 = nodes_l1 @ W2_00 -> A
    gemm128<<<(NNODES + 127) / 128, 256, 131072>>>(bufB, W2_00, bufA, NNODES);
    // 6) D = adj @ h3
    zero_kernel<<<(NB4 + 255) / 256, 256>>>((float4*)bufD, NB4);
    spmm_atomic<<<(adj_nnz + 7) / 8, 256>>>(adj_rows, adj_cols, adj_vals, adj_nnz, bufA, bufD);
    // 7) h4 = edges_l1 @ W2_10 -> A  (200k rows)
    gemm128<<<(NEDGES + 127) / 128, 256, 131072>>>(bufC, W2_10, bufA, NEDGES);
    // 8) D += inc @ h4
    spmm_atomic<<<(inc_nnz + 7) / 8, 256>>>(inc_rows, inc_cols, inc_vals, inc_nnz, bufA, bufD);
    // 9) out = sigmoid(D)
    sigmoid_kernel<<<(NB4 + 255) / 256, 256>>>((const float4*)bufD, (float4*)d_out, NB4);
}

// round 2
// speedup vs baseline: 1.4895x; 1.4895x over previous
#include <cuda_runtime.h>
#include <cstdint>

#define CDIM    128
#define NNODES  100000
#define NEDGES  200000
#define ADJ_MAX 3200000
#define INC_MAX 400000

typedef unsigned long long ull;

// ---------------- scratch (__device__ globals: allocation-free) ----------------
__device__ __align__(128) float g_bufA[(size_t)NEDGES * CDIM];  // h4 (200k)
__device__ __align__(128) float g_bufB[(size_t)NNODES * CDIM];  // nodes_l1
__device__ __align__(128) float g_bufC[(size_t)NEDGES * CDIM];  // edges_l1
__device__ __align__(128) float g_bufD[(size_t)NNODES * CDIM];  // h1/h2/h3

// CSR: adj (rows=nodes), incT (rows=edges), inc (rows=nodes)
__device__ int   g_adj_ptr[NNODES + 1];
__device__ int   g_adj_ci [ADJ_MAX];
__device__ float g_adj_cv [ADJ_MAX];
__device__ int   g_it_ptr [NEDGES + 1];
__device__ int   g_it_ci  [INC_MAX];
__device__ float g_it_cv  [INC_MAX];
__device__ int   g_in_ptr [NNODES + 1];
__device__ int   g_in_ci  [INC_MAX];
__device__ float g_in_cv  [INC_MAX];
__device__ int   g_cnt  [NEDGES];       // shared scratch (sequential reuse)
__device__ int   g_work [NEDGES + 1];
__device__ int   g_sums [64];

// ---------------- packed f32x2 helpers ----------------
__device__ __forceinline__ ull fma2(ull a, ull b, ull c) {
    ull d;
    asm("fma.rn.f32x2 %0, %1, %2, %3;" : "=l"(d) : "l"(a), "l"(b), "l"(c));
    return d;
}
__device__ __forceinline__ ull dup2(float x) {
    ull d;
    asm("mov.b64 %0, {%1, %1};" : "=l"(d) : "f"(x));
    return d;
}
__device__ __forceinline__ float2 unpack2(ull v) {
    float2 r;
    asm("mov.b64 {%0, %1}, %2;" : "=f"(r.x), "=f"(r.y) : "l"(v));
    return r;
}
__device__ __forceinline__ float sigf(float x) { return 1.f / (1.f + __expf(-x)); }

// ---------------- GEMM: out[M,128] = A[M,128] @ W[128,128] ----------------
__global__ __launch_bounds__(256, 1) void gemm128(const float* __restrict__ A,
                                                  const float* __restrict__ W,
                                                  float* __restrict__ out, int M)
{
    extern __shared__ float smem[];
    float* sA = smem;            // 64 KB swizzled transposed A tile
    float* sW = smem + 16384;    // 64 KB W [k][n]

    const int tid  = threadIdx.x;
    const int row0 = blockIdx.x * 128;

    #pragma unroll
    for (int i = 0; i < 16; ++i) {
        int e = tid + i * 256;
        reinterpret_cast<float4*>(sW)[e] = reinterpret_cast<const float4*>(W)[e];
    }
    #pragma unroll
    for (int i = 0; i < 16; ++i) {
        int e  = tid + i * 256;
        int r  = e >> 5;
        int kq = e & 31;
        float4 v = make_float4(0.f, 0.f, 0.f, 0.f);
        int grow = row0 + r;
        if (grow < M) v = reinterpret_cast<const float4*>(A)[(size_t)grow * 32 + kq];
        float vv[4] = {v.x, v.y, v.z, v.w};
        #pragma unroll
        for (int j = 0; j < 4; ++j) {
            int k = kq * 4 + j;
            int chunk = (r >> 2) ^ (k >> 2);
            sA[k * 128 + chunk * 4 + (r & 3)] = vv[j];
        }
    }
    __syncthreads();

    const int tx = tid & 15;
    const int ty = tid >> 4;
    const int cbase = tx * 8;
    const int c0 = ty * 2;

    ull acc[4][8];
    #pragma unroll
    for (int rp = 0; rp < 4; ++rp)
        #pragma unroll
        for (int c = 0; c < 8; ++c) acc[rp][c] = 0ull;

    #pragma unroll 8
    for (int k = 0; k < 128; ++k) {
        int s = k >> 2;
        ulonglong2 alo = *reinterpret_cast<const ulonglong2*>(&sA[k * 128 + ((c0 ^ s) << 2)]);
        ulonglong2 ahi = *reinterpret_cast<const ulonglong2*>(&sA[k * 128 + (((c0 + 1) ^ s) << 2)]);
        float4 w0 = *reinterpret_cast<const float4*>(&sW[k * 128 + cbase]);
        float4 w1 = *reinterpret_cast<const float4*>(&sW[k * 128 + cbase + 4]);
        ull wd[8] = {dup2(w0.x), dup2(w0.y), dup2(w0.z), dup2(w0.w),
                     dup2(w1.x), dup2(w1.y), dup2(w1.z), dup2(w1.w)};
        ull a2[4] = {alo.x, alo.y, ahi.x, ahi.y};
        #pragma unroll
        for (int rp = 0; rp < 4; ++rp)
            #pragma unroll
            for (int c = 0; c < 8; ++c)
                acc[rp][c] = fma2(a2[rp], wd[c], acc[rp][c]);
    }

    #pragma unroll
    for (int rp = 0; rp < 4; ++rp) {
        float2 f[8];
        #pragma unroll
        for (int c = 0; c < 8; ++c) f[c] = unpack2(acc[rp][c]);
        int grow = row0 + ty * 8 + rp * 2;
        if (grow < M) {
            *reinterpret_cast<float4*>(&out[(size_t)grow * 128 + cbase]) =
                make_float4(f[0].x, f[1].x, f[2].x, f[3].x);
            *reinterpret_cast<float4*>(&out[(size_t)grow * 128 + cbase + 4]) =
                make_float4(f[4].x, f[5].x, f[6].x, f[7].x);
        }
        if (grow + 1 < M) {
            *reinterpret_cast<float4*>(&out[(size_t)(grow + 1) * 128 + cbase]) =
                make_float4(f[0].y, f[1].y, f[2].y, f[3].y);
            *reinterpret_cast<float4*>(&out[(size_t)(grow + 1) * 128 + cbase + 4]) =
                make_float4(f[4].y, f[5].y, f[6].y, f[7].y);
        }
    }
}

// ---------------- CSR build ----------------
__global__ __launch_bounds__(256) void hist_kernel(const int* __restrict__ rows, int nnz,
                                                   int* __restrict__ cnt)
{
    int i = blockIdx.x * blockDim.x + threadIdx.x;
    if (i < nnz) atomicAdd(&cnt[rows[i]], 1);
}

// per-chunk (4096 elems) exclusive scan; block total -> sums[b]
__global__ __launch_bounds__(1024) void scan_chunk(const int* __restrict__ in,
                                                   int* __restrict__ out,
                                                   int* __restrict__ sums, int n)
{
    __shared__ int sh[1024];
    int t = threadIdx.x;
    int base = blockIdx.x * 4096;
    int idx = base + t * 4;
    int a0 = (idx     < n) ? in[idx]     : 0;
    int a1 = (idx + 1 < n) ? in[idx + 1] : 0;
    int a2 = (idx + 2 < n) ? in[idx + 2] : 0;
    int a3 = (idx + 3 < n) ? in[idx + 3] : 0;
    int s = a0 + a1 + a2 + a3;
    sh[t] = s;
    __syncthreads();
    for (int off = 1; off < 1024; off <<= 1) {
        int v = (t >= off) ? sh[t - off] : 0;
        __syncthreads();
        sh[t] += v;
        __syncthreads();
    }
    int excl = sh[t] - s;
    if (idx     < n) out[idx]     = excl;
    if (idx + 1 < n) out[idx + 1] = excl + a0;
    if (idx + 2 < n) out[idx + 2] = excl + a0 + a1;
    if (idx + 3 < n) out[idx + 3] = excl + a0 + a1 + a2;
    if (t == 1023) sums[blockIdx.x] = sh[1023];
}

__global__ __launch_bounds__(64) void scan_sums(int* __restrict__ sums, int nB)
{
    __shared__ int sh[64];
    int t = threadIdx.x;
    int v = (t < nB) ? sums[t] : 0;
    sh[t] = v;
    __syncthreads();
    for (int off = 1; off < 64; off <<= 1) {
        int u = (t >= off) ? sh[t - off] : 0;
        __syncthreads();
        sh[t] += u;
        __syncthreads();
    }
    if (t < nB) sums[t] = sh[t] - v;
}

__global__ __launch_bounds__(256) void add_base(int* __restrict__ ptr,
                                                const int* __restrict__ sums,
                                                int n, int nnz)
{
    int i = blockIdx.x * blockDim.x + threadIdx.x;
    if (i < n) ptr[i] += sums[i >> 12];
    if (i == 0) ptr[n] = nnz;
}

__global__ __launch_bounds__(256) void scatter_kernel(const int* __restrict__ rows,
                                                      const int* __restrict__ cols,
                                                      const float* __restrict__ vals, int nnz,
                                                      int* __restrict__ work,
                                                      int* __restrict__ ci,
                                                      float* __restrict__ cv)
{
    int i = blockIdx.x * blockDim.x + threadIdx.x;
    if (i >= nnz) return;
    int p = atomicAdd(&work[rows[i]], 1);
    ci[p] = cols[i];
    cv[p] = vals[i];
}

// ---------------- CSR SpMM: warp per row, register accumulation ----------------
__global__ __launch_bounds__(256) void spmm_csr(const int* __restrict__ ptr,
                                                const int* __restrict__ ci,
                                                const float* __restrict__ cv,
                                                const float4* __restrict__ X,
                                                float4* __restrict__ out,
                                                int nrows, int applySig)
{
    __shared__ int   sc[8][32];
    __shared__ float sv[8][32];
    int w    = (blockIdx.x * blockDim.x + threadIdx.x) >> 5;
    int lane = threadIdx.x & 31;
    int wl   = threadIdx.x >> 5;
    if (w >= nrows) return;
    int start = ptr[w], end = ptr[w + 1];
    float4 acc = make_float4(0.f, 0.f, 0.f, 0.f);
    for (int i = start; i < end; i += 32) {
        int take = min(32, end - i);
        if (lane < take) { sc[wl][lane] = ci[i + lane]; sv[wl][lane] = cv[i + lane]; }
        __syncwarp();
        #pragma unroll 4
        for (int j = 0; j < take; ++j) {
            int c = sc[wl][j];
            float v = sv[wl][j];
            float4 xv = __ldg(&X[(size_t)c * 32 + lane]);
            acc.x += v * xv.x; acc.y += v * xv.y; acc.z += v * xv.z; acc.w += v * xv.w;
        }
        __syncwarp();
    }
    if (applySig) {
        acc.x = sigf(acc.x); acc.y = sigf(acc.y); acc.z = sigf(acc.z); acc.w = sigf(acc.w);
    }
    out[(size_t)w * 32 + lane] = acc;
}

// out = sigmoid(adjCSR @ XA + incCSR @ XB), one pass
__global__ __launch_bounds__(256) void spmm_dual(const int* __restrict__ ptrA,
                                                 const int* __restrict__ ciA,
                                                 const float* __restrict__ cvA,
                                                 const float4* __restrict__ XA,
                                                 const int* __restrict__ ptrB,
                                                 const int* __restrict__ ciB,
                                                 const float* __restrict__ cvB,
                                                 const float4* __restrict__ XB,
                                                 float4* __restrict__ out, int nrows)
{
    __shared__ int   sc[8][32];
    __shared__ float sv[8][32];
    int w    = (blockIdx.x * blockDim.x + threadIdx.x) >> 5;
    int lane = threadIdx.x & 31;
    int wl   = threadIdx.x >> 5;
    if (w >= nrows) return;
    float4 acc = make_float4(0.f, 0.f, 0.f, 0.f);

    int start = ptrA[w], end = ptrA[w + 1];
    for (int i = start; i < end; i += 32) {
        int take = min(32, end - i);
        if (lane < take) { sc[wl][lane] = ciA[i + lane]; sv[wl][lane] = cvA[i + lane]; }
        __syncwarp();
        #pragma unroll 4
        for (int j = 0; j < take; ++j) {
            int c = sc[wl][j];
            float v = sv[wl][j];
            float4 xv = __ldg(&XA[(size_t)c * 32 + lane]);
            acc.x += v * xv.x; acc.y += v * xv.y; acc.z += v * xv.z; acc.w += v * xv.w;
        }
        __syncwarp();
    }
    start = ptrB[w]; end = ptrB[w + 1];
    for (int i = start; i < end; i += 32) {
        int take = min(32, end - i);
        if (lane < take) { sc[wl][lane] = ciB[i + lane]; sv[wl][lane] = cvB[i + lane]; }
        __syncwarp();
        #pragma unroll 4
        for (int j = 0; j < take; ++j) {
            int c = sc[wl][j];
            float v = sv[wl][j];
            float4 xv = __ldg(&XB[(size_t)c * 32 + lane]);
            acc.x += v * xv.x; acc.y += v * xv.y; acc.z += v * xv.z; acc.w += v * xv.w;
        }
        __syncwarp();
    }
    acc.x = sigf(acc.x); acc.y = sigf(acc.y); acc.z = sigf(acc.z); acc.w = sigf(acc.w);
    out[(size_t)w * 32 + lane] = acc;
}

// ---------------- host ----------------
static void build_csr(const int* rows, const int* cols, const float* vals, int nnz,
                      int n, int* cnt, int* ptr, int* work, int* sums,
                      int* ci, float* cv)
{
    cudaMemsetAsync(cnt, 0, (size_t)n * sizeof(int));
    hist_kernel<<<(nnz + 255) / 256, 256>>>(rows, nnz, cnt);
    int nB = (n + 4095) / 4096;
    scan_chunk<<<nB, 1024>>>(cnt, ptr, sums, n);
    scan_sums<<<1, 64>>>(sums, nB);
    add_base<<<(n + 256) / 256, 256>>>(ptr, sums, n, nnz);
    cudaMemcpyAsync(work, ptr, (size_t)n * sizeof(int), cudaMemcpyDeviceToDevice);
    scatter_kernel<<<(nnz + 255) / 256, 256>>>(rows, cols, vals, nnz, work, ci, cv);
}

extern "C" void kernel_launch(void* const* d_in, const int* in_sizes, int n_in,
                              void* d_out, int out_size)
{
    const float* x        = (const float*)d_in[0];
    const float* W1_00    = (const float*)d_in[1];
    const float* W1_01    = (const float*)d_in[2];
    const float* W2_00    = (const float*)d_in[3];
    const float* W2_10    = (const float*)d_in[4];
    const int*   adj_rows = (const int*)  d_in[5];
    const int*   adj_cols = (const int*)  d_in[6];
    const float* adj_vals = (const float*)d_in[7];
    const int*   inc_rows = (const int*)  d_in[8];
    const int*   inc_cols = (const int*)  d_in[9];
    const float* inc_vals = (const float*)d_in[10];
    const int adj_nnz = in_sizes[5];
    const int inc_nnz = in_sizes[8];
    const int nodes   = in_sizes[0] / CDIM;   // 100000
    const int edges   = NEDGES;               // 200000

    float *bufA, *bufB, *bufC, *bufD;
    int *adj_ptr, *adj_ci, *it_ptr, *it_ci, *in_ptr, *in_ci, *cnt, *work, *sums;
    float *adj_cv, *it_cv, *in_cv;
    cudaGetSymbolAddress((void**)&bufA, g_bufA);
    cudaGetSymbolAddress((void**)&bufB, g_bufB);
    cudaGetSymbolAddress((void**)&bufC, g_bufC);
    cudaGetSymbolAddress((void**)&bufD, g_bufD);
    cudaGetSymbolAddress((void**)&adj_ptr, g_adj_ptr);
    cudaGetSymbolAddress((void**)&adj_ci,  g_adj_ci);
    cudaGetSymbolAddress((void**)&adj_cv,  g_adj_cv);
    cudaGetSymbolAddress((void**)&it_ptr,  g_it_ptr);
    cudaGetSymbolAddress((void**)&it_ci,   g_it_ci);
    cudaGetSymbolAddress((void**)&it_cv,   g_it_cv);
    cudaGetSymbolAddress((void**)&in_ptr,  g_in_ptr);
    cudaGetSymbolAddress((void**)&in_ci,   g_in_ci);
    cudaGetSymbolAddress((void**)&in_cv,   g_in_cv);
    cudaGetSymbolAddress((void**)&cnt,  g_cnt);
    cudaGetSymbolAddress((void**)&work, g_work);
    cudaGetSymbolAddress((void**)&sums, g_sums);

    cudaFuncSetAttribute(gemm128, cudaFuncAttributeMaxDynamicSharedMemorySize, 131072);

    // CSR builds
    build_csr(adj_rows, adj_cols, adj_vals, adj_nnz, nodes, cnt, adj_ptr, work, sums, adj_ci, adj_cv);
    build_csr(inc_cols, inc_rows, inc_vals, inc_nnz, edges, cnt, it_ptr,  work, sums, it_ci,  it_cv);
    build_csr(inc_rows, inc_cols, inc_vals, inc_nnz, nodes, cnt, in_ptr,  work, sums, in_ci,  in_cv);

    // Level 1
    gemm128<<<(nodes + 127) / 128, 256, 131072>>>(x, W1_00, bufD, nodes);
    spmm_csr<<<(nodes + 7) / 8, 256>>>(adj_ptr, adj_ci, adj_cv,
                                       (const float4*)bufD, (float4*)bufB, nodes, 1);
    gemm128<<<(nodes + 127) / 128, 256, 131072>>>(x, W1_01, bufD, nodes);
    spmm_csr<<<(edges + 7) / 8, 256>>>(it_ptr, it_ci, it_cv,
                                       (const float4*)bufD, (float4*)bufC, edges, 1);
    // Level 2
    gemm128<<<(nodes + 127) / 128, 256, 131072>>>(bufB, W2_00, bufD, nodes);
    gemm128<<<(edges + 127) / 128, 256, 131072>>>(bufC, W2_10, bufA, edges);
    // Merge + sigmoid, single pass
    spmm_dual<<<(nodes + 7) / 8, 256>>>(adj_ptr, adj_ci, adj_cv, (const float4*)bufD,
                                        in_ptr, in_ci, in_cv, (const float4*)bufA,
                                        (float4*)d_out, nodes);
}

// round 3
// speedup vs baseline: 1.8870x; 1.2669x over previous
#include <cuda_runtime.h>
#include <cuda_fp16.h>
#include <cstdint>

#define CDIM    128
#define NNODES  100000
#define NEDGES  200000
#define ADJ_MAX 3200000
#define INC_MAX 400000

typedef unsigned long long ull;

// ---------------- scratch (__device__ globals: allocation-free) ----------------
__device__ __align__(128) float  g_bufB[(size_t)NNODES * CDIM];  // nodes_l1 (fp32)
__device__ __align__(128) float  g_bufC[(size_t)NEDGES * CDIM];  // edges_l1 (fp32)
__device__ __align__(128) __half g_hX[(size_t)NEDGES * CDIM];    // h1/h2/h4 (fp16)
__device__ __align__(128) __half g_hY[(size_t)NNODES * CDIM];    // h3 (fp16)

// CSR: adj (rows=nodes), incT (rows=edges), inc (rows=nodes); (col, val) packed int2
__device__ int  g_adj_ptr[NNODES + 1];
__device__ int2 g_adj_e  [ADJ_MAX];
__device__ int  g_it_ptr [NEDGES + 1];
__device__ int2 g_it_e   [INC_MAX];
__device__ int  g_in_ptr [NNODES + 1];
__device__ int2 g_in_e   [INC_MAX];
__device__ int  g_cnt  [NEDGES];
__device__ int  g_work [NEDGES + 1];
__device__ int  g_sums [64];

// ---------------- packed f32x2 helpers ----------------
__device__ __forceinline__ ull fma2(ull a, ull b, ull c) {
    ull d;
    asm("fma.rn.f32x2 %0, %1, %2, %3;" : "=l"(d) : "l"(a), "l"(b), "l"(c));
    return d;
}
__device__ __forceinline__ ull dup2(float x) {
    ull d;
    asm("mov.b64 %0, {%1, %1};" : "=l"(d) : "f"(x));
    return d;
}
__device__ __forceinline__ float2 unpack2(ull v) {
    float2 r;
    asm("mov.b64 {%0, %1}, %2;" : "=f"(r.x), "=f"(r.y) : "l"(v));
    return r;
}
__device__ __forceinline__ float sigf(float x) { return 1.f / (1.f + __expf(-x)); }
__device__ __forceinline__ unsigned h2u(__half2 h) { return *reinterpret_cast<unsigned*>(&h); }

// ---------------- GEMM: outH[M,128] = half( A[M,128] @ W[128,128] ), fp32 accumulate ----
__global__ __launch_bounds__(256, 1) void gemm128h(const float* __restrict__ A,
                                                   const float* __restrict__ W,
                                                   __half* __restrict__ out, int M)
{
    extern __shared__ float smem[];
    float* sA = smem;            // 64 KB swizzled transposed A tile
    float* sW = smem + 16384;    // 64 KB W [k][n]

    const int tid  = threadIdx.x;
    const int row0 = blockIdx.x * 128;

    #pragma unroll
    for (int i = 0; i < 16; ++i) {
        int e = tid + i * 256;
        reinterpret_cast<float4*>(sW)[e] = reinterpret_cast<const float4*>(W)[e];
    }
    #pragma unroll
    for (int i = 0; i < 16; ++i) {
        int e  = tid + i * 256;
        int r  = e >> 5;
        int kq = e & 31;
        float4 v = make_float4(0.f, 0.f, 0.f, 0.f);
        int grow = row0 + r;
        if (grow < M) v = reinterpret_cast<const float4*>(A)[(size_t)grow * 32 + kq];
        float vv[4] = {v.x, v.y, v.z, v.w};
        #pragma unroll
        for (int j = 0; j < 4; ++j) {
            int k = kq * 4 + j;
            int chunk = (r >> 2) ^ (k >> 2);
            sA[k * 128 + chunk * 4 + (r & 3)] = vv[j];
        }
    }
    __syncthreads();

    const int tx = tid & 15;
    const int ty = tid >> 4;
    const int cbase = tx * 8;
    const int c0 = ty * 2;

    ull acc[4][8];
    #pragma unroll
    for (int rp = 0; rp < 4; ++rp)
        #pragma unroll
        for (int c = 0; c < 8; ++c) acc[rp][c] = 0ull;

    #pragma unroll 8
    for (int k = 0; k < 128; ++k) {
        int s = k >> 2;
        ulonglong2 alo = *reinterpret_cast<const ulonglong2*>(&sA[k * 128 + ((c0 ^ s) << 2)]);
        ulonglong2 ahi = *reinterpret_cast<const ulonglong2*>(&sA[k * 128 + (((c0 + 1) ^ s) << 2)]);
        float4 w0 = *reinterpret_cast<const float4*>(&sW[k * 128 + cbase]);
        float4 w1 = *reinterpret_cast<const float4*>(&sW[k * 128 + cbase + 4]);
        ull wd[8] = {dup2(w0.x), dup2(w0.y), dup2(w0.z), dup2(w0.w),
                     dup2(w1.x), dup2(w1.y), dup2(w1.z), dup2(w1.w)};
        ull a2[4] = {alo.x, alo.y, ahi.x, ahi.y};
        #pragma unroll
        for (int rp = 0; rp < 4; ++rp)
            #pragma unroll
            for (int c = 0; c < 8; ++c)
                acc[rp][c] = fma2(a2[rp], wd[c], acc[rp][c]);
    }

    #pragma unroll
    for (int rp = 0; rp < 4; ++rp) {
        float2 f[8];
        #pragma unroll
        for (int c = 0; c < 8; ++c) f[c] = unpack2(acc[rp][c]);
        int grow = row0 + ty * 8 + rp * 2;
        if (grow < M) {
            uint4 o = make_uint4(h2u(__floats2half2_rn(f[0].x, f[1].x)),
                                 h2u(__floats2half2_rn(f[2].x, f[3].x)),
                                 h2u(__floats2half2_rn(f[4].x, f[5].x)),
                                 h2u(__floats2half2_rn(f[6].x, f[7].x)));
            *reinterpret_cast<uint4*>(&out[(size_t)grow * 128 + cbase]) = o;
        }
        if (grow + 1 < M) {
            uint4 o = make_uint4(h2u(__floats2half2_rn(f[0].y, f[1].y)),
                                 h2u(__floats2half2_rn(f[2].y, f[3].y)),
                                 h2u(__floats2half2_rn(f[4].y, f[5].y)),
                                 h2u(__floats2half2_rn(f[6].y, f[7].y)));
            *reinterpret_cast<uint4*>(&out[(size_t)(grow + 1) * 128 + cbase]) = o;
        }
    }
}

// ---------------- CSR build ----------------
__global__ __launch_bounds__(256) void hist_kernel(const int* __restrict__ rows, int nnz,
                                                   int* __restrict__ cnt)
{
    int i = blockIdx.x * blockDim.x + threadIdx.x;
    if (i < nnz) atomicAdd(&cnt[rows[i]], 1);
}

__global__ __launch_bounds__(1024) void scan_chunk(const int* __restrict__ in,
                                                   int* __restrict__ out,
                                                   int* __restrict__ sums, int n)
{
    __shared__ int sh[1024];
    int t = threadIdx.x;
    int base = blockIdx.x * 4096;
    int idx = base + t * 4;
    int a0 = (idx     < n) ? in[idx]     : 0;
    int a1 = (idx + 1 < n) ? in[idx + 1] : 0;
    int a2 = (idx + 2 < n) ? in[idx + 2] : 0;
    int a3 = (idx + 3 < n) ? in[idx + 3] : 0;
    int s = a0 + a1 + a2 + a3;
    sh[t] = s;
    __syncthreads();
    for (int off = 1; off < 1024; off <<= 1) {
        int v = (t >= off) ? sh[t - off] : 0;
        __syncthreads();
        sh[t] += v;
        __syncthreads();
    }
    int excl = sh[t] - s;
    if (idx     < n) out[idx]     = excl;
    if (idx + 1 < n) out[idx + 1] = excl + a0;
    if (idx + 2 < n) out[idx + 2] = excl + a0 + a1;
    if (idx + 3 < n) out[idx + 3] = excl + a0 + a1 + a2;
    if (t == 1023) sums[blockIdx.x] = sh[1023];
}

__global__ __launch_bounds__(64) void scan_sums(int* __restrict__ sums, int nB)
{
    __shared__ int sh[64];
    int t = threadIdx.x;
    int v = (t < nB) ? sums[t] : 0;
    sh[t] = v;
    __syncthreads();
    for (int off = 1; off < 64; off <<= 1) {
        int u = (t >= off) ? sh[t - off] : 0;
        __syncthreads();
        sh[t] += u;
        __syncthreads();
    }
    if (t < nB) sums[t] = sh[t] - v;
}

__global__ __launch_bounds__(256) void add_base_work(int* __restrict__ ptr,
                                                     int* __restrict__ work,
                                                     const int* __restrict__ sums,
                                                     int n, int nnz)
{
    int i = blockIdx.x * blockDim.x + threadIdx.x;
    if (i < n) {
        int v = ptr[i] + sums[i >> 12];
        ptr[i]  = v;
        work[i] = v;
    }
    if (i == 0) ptr[n] = nnz;
}

__global__ __launch_bounds__(256) void scatter_kernel(const int* __restrict__ rows,
                                                      const int* __restrict__ cols,
                                                      const float* __restrict__ vals, int nnz,
                                                      int* __restrict__ work,
                                                      int2* __restrict__ e)
{
    int i = blockIdx.x * blockDim.x + threadIdx.x;
    if (i >= nnz) return;
    int p = atomicAdd(&work[rows[i]], 1);
    e[p] = make_int2(cols[i], __float_as_int(vals[i]));
}

// ---------------- CSR SpMM (fp16 features): warp per row ----------------
__device__ __forceinline__ void gather_fma(float4& acc, int2 t,
                                           const uint2* __restrict__ Xu, int lane)
{
    float v  = __int_as_float(t.y);
    uint2 u  = __ldg(&Xu[(size_t)t.x * 32 + lane]);
    float2 f0 = __half22float2(*reinterpret_cast<__half2*>(&u.x));
    float2 f1 = __half22float2(*reinterpret_cast<__half2*>(&u.y));
    acc.x += v * f0.x; acc.y += v * f0.y; acc.z += v * f1.x; acc.w += v * f1.y;
}

__global__ __launch_bounds__(256) void spmm_h(const int* __restrict__ ptr,
                                              const int2* __restrict__ e,
                                              const __half* __restrict__ X,
                                              float4* __restrict__ out,
                                              int nrows, int applySig)
{
    __shared__ int2 se[8][32];
    int w    = (blockIdx.x * blockDim.x + threadIdx.x) >> 5;
    int lane = threadIdx.x & 31;
    int wl   = threadIdx.x >> 5;
    if (w >= nrows) return;
    const uint2* Xu = reinterpret_cast<const uint2*>(X);
    int start = ptr[w], end = ptr[w + 1];
    float4 acc = make_float4(0.f, 0.f, 0.f, 0.f);
    for (int i = start; i < end; i += 32) {
        int take = min(32, end - i);
        if (lane < take) se[wl][lane] = e[i + lane];
        __syncwarp();
        if (take == 32) {
            #pragma unroll 8
            for (int j = 0; j < 32; ++j) gather_fma(acc, se[wl][j], Xu, lane);
        } else {
            for (int j = 0; j < take; ++j) gather_fma(acc, se[wl][j], Xu, lane);
        }
        __syncwarp();
    }
    if (applySig) {
        acc.x = sigf(acc.x); acc.y = sigf(acc.y); acc.z = sigf(acc.z); acc.w = sigf(acc.w);
    }
    out[(size_t)w * 32 + lane] = acc;
}

// out = sigmoid(adjCSR @ XA + incCSR @ XB), one pass, fp16 features
__global__ __launch_bounds__(256) void spmm_dual_h(const int* __restrict__ ptrA,
                                                   const int2* __restrict__ eA,
                                                   const __half* __restrict__ XA,
                                                   const int* __restrict__ ptrB,
                                                   const int2* __restrict__ eB,
                                                   const __half* __restrict__ XB,
                                                   float4* __restrict__ out, int nrows)
{
    __shared__ int2 se[8][32];
    int w    = (blockIdx.x * blockDim.x + threadIdx.x) >> 5;
    int lane = threadIdx.x & 31;
    int wl   = threadIdx.x >> 5;
    if (w >= nrows) return;
    const uint2* XuA = reinterpret_cast<const uint2*>(XA);
    const uint2* XuB = reinterpret_cast<const uint2*>(XB);
    float4 acc = make_float4(0.f, 0.f, 0.f, 0.f);

    int start = ptrA[w], end = ptrA[w + 1];
    for (int i = start; i < end; i += 32) {
        int take = min(32, end - i);
        if (lane < take) se[wl][lane] = eA[i + lane];
        __syncwarp();
        if (take == 32) {
            #pragma unroll 8
            for (int j = 0; j < 32; ++j) gather_fma(acc, se[wl][j], XuA, lane);
        } else {
            for (int j = 0; j < take; ++j) gather_fma(acc, se[wl][j], XuA, lane);
        }
        __syncwarp();
    }
    start = ptrB[w]; end = ptrB[w + 1];
    for (int i = start; i < end; i += 32) {
        int take = min(32, end - i);
        if (lane < take) se[wl][lane] = eB[i + lane];
        __syncwarp();
        for (int j = 0; j < take; ++j) gather_fma(acc, se[wl][j], XuB, lane);
        __syncwarp();
    }
    acc.x = sigf(acc.x); acc.y = sigf(acc.y); acc.z = sigf(acc.z); acc.w = sigf(acc.w);
    out[(size_t)w * 32 + lane] = acc;
}

// ---------------- host ----------------
static void build_csr(const int* rows, const int* cols, const float* vals, int nnz,
                      int n, int* cnt, int* ptr, int* work, int* sums, int2* e)
{
    cudaMemsetAsync(cnt, 0, (size_t)n * sizeof(int));
    hist_kernel<<<(nnz + 255) / 256, 256>>>(rows, nnz, cnt);
    int nB = (n + 4095) / 4096;
    scan_chunk<<<nB, 1024>>>(cnt, ptr, sums, n);
    scan_sums<<<1, 64>>>(sums, nB);
    add_base_work<<<(n + 256) / 256, 256>>>(ptr, work, sums, n, nnz);
    scatter_kernel<<<(nnz + 255) / 256, 256>>>(rows, cols, vals, nnz, work, e);
}

extern "C" void kernel_launch(void* const* d_in, const int* in_sizes, int n_in,
                              void* d_out, int out_size)
{
    const float* x        = (const float*)d_in[0];
    const float* W1_00    = (const float*)d_in[1];
    const float* W1_01    = (const float*)d_in[2];
    const float* W2_00    = (const float*)d_in[3];
    const float* W2_10    = (const float*)d_in[4];
    const int*   adj_rows = (const int*)  d_in[5];
    const int*   adj_cols = (const int*)  d_in[6];
    const float* adj_vals = (const float*)d_in[7];
    const int*   inc_rows = (const int*)  d_in[8];
    const int*   inc_cols = (const int*)  d_in[9];
    const float* inc_vals = (const float*)d_in[10];
    const int adj_nnz = in_sizes[5];
    const int inc_nnz = in_sizes[8];
    const int nodes   = in_sizes[0] / CDIM;   // 100000
    const int edges   = NEDGES;               // 200000

    float *bufB, *bufC;
    __half *hX, *hY;
    int *adj_ptr, *it_ptr, *in_ptr, *cnt, *work, *sums;
    int2 *adj_e, *it_e, *in_e;
    cudaGetSymbolAddress((void**)&bufB, g_bufB);
    cudaGetSymbolAddress((void**)&bufC, g_bufC);
    cudaGetSymbolAddress((void**)&hX,   g_hX);
    cudaGetSymbolAddress((void**)&hY,   g_hY);
    cudaGetSymbolAddress((void**)&adj_ptr, g_adj_ptr);
    cudaGetSymbolAddress((void**)&adj_e,   g_adj_e);
    cudaGetSymbolAddress((void**)&it_ptr,  g_it_ptr);
    cudaGetSymbolAddress((void**)&it_e,    g_it_e);
    cudaGetSymbolAddress((void**)&in_ptr,  g_in_ptr);
    cudaGetSymbolAddress((void**)&in_e,    g_in_e);
    cudaGetSymbolAddress((void**)&cnt,  g_cnt);
    cudaGetSymbolAddress((void**)&work, g_work);
    cudaGetSymbolAddress((void**)&sums, g_sums);

    cudaFuncSetAttribute(gemm128h, cudaFuncAttributeMaxDynamicSharedMemorySize, 131072);

    // CSR builds
    build_csr(adj_rows, adj_cols, adj_vals, adj_nnz, nodes, cnt, adj_ptr, work, sums, adj_e);
    build_csr(inc_cols, inc_rows, inc_vals, inc_nnz, edges, cnt, it_ptr,  work, sums, it_e);
    build_csr(inc_rows, inc_cols, inc_vals, inc_nnz, nodes, cnt, in_ptr,  work, sums, in_e);

    // Level 1
    gemm128h<<<(nodes + 127) / 128, 256, 131072>>>(x, W1_00, hX, nodes);
    spmm_h<<<(nodes + 7) / 8, 256>>>(adj_ptr, adj_e, hX, (float4*)bufB, nodes, 1);
    gemm128h<<<(nodes + 127) / 128, 256, 131072>>>(x, W1_01, hX, nodes);
    spmm_h<<<(edges + 7) / 8, 256>>>(it_ptr, it_e, hX, (float4*)bufC, edges, 1);
    // Level 2
    gemm128h<<<(nodes + 127) / 128, 256, 131072>>>(bufB, W2_00, hY, nodes);
    gemm128h<<<(edges + 127) / 128, 256, 131072>>>(bufC, W2_10, hX, edges);
    // Merge + sigmoid
    spmm_dual_h<<<(nodes + 7) / 8, 256>>>(adj_ptr, adj_e, hY,
                                          in_ptr, in_e, hX,
                                          (float4*)d_out, nodes);
}

// round 4
// speedup vs baseline: 2.8274x; 1.4984x over previous
#include <cuda_runtime.h>
#include <cuda_fp16.h>
#include <mma.h>
#include <cstdint>

#define CDIM    128
#define NNODES  100000
#define NEDGES  200000
#define ADJ_MAX 3200000
#define INC_MAX 400000
#define LDH     136   // padded smem leading dim (halves)

using namespace nvcuda;

// ---------------- scratch (__device__ globals: allocation-free) ----------------
__device__ __align__(128) __half g_hx [(size_t)NNODES * CDIM];   // x (fp16)
__device__ __align__(128) __half g_hB [(size_t)NNODES * CDIM];   // nodes_l1 (fp16)
__device__ __align__(128) __half g_hC [(size_t)NEDGES * CDIM];   // edges_l1 (fp16)
__device__ __align__(128) __half g_hX [(size_t)NEDGES * CDIM];   // h1/h2/h4 (fp16)
__device__ __align__(128) __half g_hY [(size_t)NNODES * CDIM];   // h3 (fp16)
__device__ __align__(128) __half g_hW [4][CDIM * CDIM];          // weights (fp16)

// CSR: adj (rows=nodes), incT (rows=edges), inc (rows=nodes); (col, val) packed int2
__device__ int  g_adj_ptr[NNODES + 1];
__device__ int2 g_adj_e  [ADJ_MAX];
__device__ int  g_it_ptr [NEDGES + 1];
__device__ int2 g_it_e   [INC_MAX];
__device__ int  g_in_ptr [NNODES + 1];
__device__ int2 g_in_e   [INC_MAX];
__device__ int  g_cnt  [NEDGES];
__device__ int  g_work [NEDGES + 1];
__device__ int  g_sums [64];

__device__ __forceinline__ float sigf(float x) { return 1.f / (1.f + __expf(-x)); }
__device__ __forceinline__ unsigned h2u(__half2 h) { return *reinterpret_cast<unsigned*>(&h); }

// ---------------- convert fp32 -> fp16 (vectorized) ----------------
__global__ __launch_bounds__(256) void f2h_kernel(const float4* __restrict__ in,
                                                  uint2* __restrict__ out, int n4)
{
    int i = blockIdx.x * blockDim.x + threadIdx.x;
    if (i < n4) {
        float4 v = in[i];
        out[i] = make_uint2(h2u(__floats2half2_rn(v.x, v.y)),
                            h2u(__floats2half2_rn(v.z, v.w)));
    }
}

// ---------------- tensor-core GEMM: outH[M,128] = half( A[M,128] @ W[128,128] ) ------
// A, W fp16; fp32 accumulate (HMMA). Block 256 thr = 8 warps; tile 128x128;
// warp tile 32x64 (2x4 wmma frags); smem staging with ld=136 padding.
__global__ __launch_bounds__(256, 1) void gemm_tc(const __half* __restrict__ A,
                                                  const __half* __restrict__ W,
                                                  __half* __restrict__ out, int M)
{
    extern __shared__ char smem[];
    __half* sA = reinterpret_cast<__half*>(smem);                    // 128 x 136 halves
    __half* sW = reinterpret_cast<__half*>(smem + 128 * LDH * 2);    // 128 x 136 halves
    float*  sO = reinterpret_cast<float*>(smem);                     // reuse: 128 x 128 f32

    const int tid  = threadIdx.x;
    const int row0 = blockIdx.x * 128;

    // stage W and A (uint4 = 8 halves per load)
    #pragma unroll
    for (int i = 0; i < 8; ++i) {
        int e = tid + i * 256;          // 0..2047
        int r = e >> 4, c = e & 15;
        uint4 v = reinterpret_cast<const uint4*>(W)[e];
        *reinterpret_cast<uint4*>(&sW[r * LDH + c * 8]) = v;
    }
    #pragma unroll
    for (int i = 0; i < 8; ++i) {
        int e = tid + i * 256;
        int r = e >> 4, c = e & 15;
        uint4 v = make_uint4(0u, 0u, 0u, 0u);
        if (row0 + r < M) v = reinterpret_cast<const uint4*>(A)[(size_t)(row0 + r) * 16 + c];
        *reinterpret_cast<uint4*>(&sA[r * LDH + c * 8]) = v;
    }
    __syncthreads();

    const int warpId = tid >> 5;
    const int wr = warpId >> 1;   // 0..3 -> rows wr*32
    const int wc = warpId & 1;    // 0..1 -> cols wc*64

    wmma::fragment<wmma::accumulator, 16, 16, 16, float> c[2][4];
    #pragma unroll
    for (int i = 0; i < 2; ++i)
        #pragma unroll
        for (int j = 0; j < 4; ++j) wmma::fill_fragment(c[i][j], 0.f);

    #pragma unroll
    for (int k = 0; k < 8; ++k) {
        wmma::fragment<wmma::matrix_a, 16, 16, 16, __half, wmma::row_major> a[2];
        wmma::fragment<wmma::matrix_b, 16, 16, 16, __half, wmma::row_major> b[4];
        #pragma unroll
        for (int i = 0; i < 2; ++i)
            wmma::load_matrix_sync(a[i], &sA[(wr * 32 + i * 16) * LDH + k * 16], LDH);
        #pragma unroll
        for (int j = 0; j < 4; ++j)
            wmma::load_matrix_sync(b[j], &sW[(k * 16) * LDH + wc * 64 + j * 16], LDH);
        #pragma unroll
        for (int i = 0; i < 2; ++i)
            #pragma unroll
            for (int j = 0; j < 4; ++j)
                wmma::mma_sync(c[i][j], a[i], b[j], c[i][j]);
    }

    __syncthreads();   // done with sA/sW; reuse as f32 output staging
    #pragma unroll
    for (int i = 0; i < 2; ++i)
        #pragma unroll
        for (int j = 0; j < 4; ++j)
            wmma::store_matrix_sync(&sO[(wr * 32 + i * 16) * 128 + wc * 64 + j * 16],
                                    c[i][j], 128, wmma::mem_row_major);
    __syncthreads();

    // convert f32 -> fp16 and write (coalesced uint2 = 4 halves)
    #pragma unroll
    for (int i = 0; i < 16; ++i) {
        int e  = tid + i * 256;        // float4 index 0..4095
        int r  = e >> 5, c4 = e & 31;
        int grow = row0 + r;
        if (grow < M) {
            float4 v = reinterpret_cast<float4*>(sO)[(size_t)r * 32 + c4];
            uint2 o = make_uint2(h2u(__floats2half2_rn(v.x, v.y)),
                                 h2u(__floats2half2_rn(v.z, v.w)));
            reinterpret_cast<uint2*>(out)[(size_t)grow * 32 + c4] = o;
        }
    }
}

// ---------------- CSR build ----------------
__global__ __launch_bounds__(256) void hist_kernel(const int* __restrict__ rows, int nnz,
                                                   int* __restrict__ cnt)
{
    int i = blockIdx.x * blockDim.x + threadIdx.x;
    if (i < nnz) atomicAdd(&cnt[rows[i]], 1);
}

__global__ __launch_bounds__(1024) void scan_chunk(const int* __restrict__ in,
                                                   int* __restrict__ out,
                                                   int* __restrict__ sums, int n)
{
    __shared__ int sh[1024];
    int t = threadIdx.x;
    int base = blockIdx.x * 4096;
    int idx = base + t * 4;
    int a0 = (idx     < n) ? in[idx]     : 0;
    int a1 = (idx + 1 < n) ? in[idx + 1] : 0;
    int a2 = (idx + 2 < n) ? in[idx + 2] : 0;
    int a3 = (idx + 3 < n) ? in[idx + 3] : 0;
    int s = a0 + a1 + a2 + a3;
    sh[t] = s;
    __syncthreads();
    for (int off = 1; off < 1024; off <<= 1) {
        int v = (t >= off) ? sh[t - off] : 0;
        __syncthreads();
        sh[t] += v;
        __syncthreads();
    }
    int excl = sh[t] - s;
    if (idx     < n) out[idx]     = excl;
    if (idx + 1 < n) out[idx + 1] = excl + a0;
    if (idx + 2 < n) out[idx + 2] = excl + a0 + a1;
    if (idx + 3 < n) out[idx + 3] = excl + a0 + a1 + a2;
    if (t == 1023) sums[blockIdx.x] = sh[1023];
}

__global__ __launch_bounds__(64) void scan_sums(int* __restrict__ sums, int nB)
{
    __shared__ int sh[64];
    int t = threadIdx.x;
    int v = (t < nB) ? sums[t] : 0;
    sh[t] = v;
    __syncthreads();
    for (int off = 1; off < 64; off <<= 1) {
        int u = (t >= off) ? sh[t - off] : 0;
        __syncthreads();
        sh[t] += u;
        __syncthreads();
    }
    if (t < nB) sums[t] = sh[t] - v;
}

__global__ __launch_bounds__(256) void add_base_work(int* __restrict__ ptr,
                                                     int* __restrict__ work,
                                                     const int* __restrict__ sums,
                                                     int n, int nnz)
{
    int i = blockIdx.x * blockDim.x + threadIdx.x;
    if (i < n) {
        int v = ptr[i] + sums[i >> 12];
        ptr[i]  = v;
        work[i] = v;
    }
    if (i == 0) ptr[n] = nnz;
}

__global__ __launch_bounds__(256) void scatter_kernel(const int* __restrict__ rows,
                                                      const int* __restrict__ cols,
                                                      const float* __restrict__ vals, int nnz,
                                                      int* __restrict__ work,
                                                      int2* __restrict__ e)
{
    int i = blockIdx.x * blockDim.x + threadIdx.x;
    if (i >= nnz) return;
    int p = atomicAdd(&work[rows[i]], 1);
    e[p] = make_int2(cols[i], __float_as_int(vals[i]));
}

// ---------------- CSR SpMM (fp16 features): warp per row ----------------
__device__ __forceinline__ void gather_fma(float4& acc, int2 t,
                                           const uint2* __restrict__ Xu, int lane)
{
    float v  = __int_as_float(t.y);
    uint2 u  = __ldg(&Xu[(size_t)t.x * 32 + lane]);
    float2 f0 = __half22float2(*reinterpret_cast<__half2*>(&u.x));
    float2 f1 = __half22float2(*reinterpret_cast<__half2*>(&u.y));
    acc.x += v * f0.x; acc.y += v * f0.y; acc.z += v * f1.x; acc.w += v * f1.y;
}

// out (fp16) = sigmoid(CSR @ X)
__global__ __launch_bounds__(256) void spmm_h(const int* __restrict__ ptr,
                                              const int2* __restrict__ e,
                                              const __half* __restrict__ X,
                                              __half* __restrict__ out, int nrows)
{
    __shared__ int2 se[8][32];
    int w    = (blockIdx.x * blockDim.x + threadIdx.x) >> 5;
    int lane = threadIdx.x & 31;
    int wl   = threadIdx.x >> 5;
    if (w >= nrows) return;
    const uint2* Xu = reinterpret_cast<const uint2*>(X);
    int start = ptr[w], end = ptr[w + 1];
    float4 acc = make_float4(0.f, 0.f, 0.f, 0.f);
    for (int i = start; i < end; i += 32) {
        int take = min(32, end - i);
        if (lane < take) se[wl][lane] = e[i + lane];
        __syncwarp();
        if (take == 32) {
            #pragma unroll 8
            for (int j = 0; j < 32; ++j) gather_fma(acc, se[wl][j], Xu, lane);
        } else {
            for (int j = 0; j < take; ++j) gather_fma(acc, se[wl][j], Xu, lane);
        }
        __syncwarp();
    }
    uint2 o = make_uint2(h2u(__floats2half2_rn(sigf(acc.x), sigf(acc.y))),
                         h2u(__floats2half2_rn(sigf(acc.z), sigf(acc.w))));
    reinterpret_cast<uint2*>(out)[(size_t)w * 32 + lane] = o;
}

// out (fp32) = sigmoid(adjCSR @ XA + incCSR @ XB), one pass
__global__ __launch_bounds__(256) void spmm_dual_h(const int* __restrict__ ptrA,
                                                   const int2* __restrict__ eA,
                                                   const __half* __restrict__ XA,
                                                   const int* __restrict__ ptrB,
                                                   const int2* __restrict__ eB,
                                                   const __half* __restrict__ XB,
                                                   float4* __restrict__ out, int nrows)
{
    __shared__ int2 se[8][32];
    int w    = (blockIdx.x * blockDim.x + threadIdx.x) >> 5;
    int lane = threadIdx.x & 31;
    int wl   = threadIdx.x >> 5;
    if (w >= nrows) return;
    const uint2* XuA = reinterpret_cast<const uint2*>(XA);
    const uint2* XuB = reinterpret_cast<const uint2*>(XB);
    float4 acc = make_float4(0.f, 0.f, 0.f, 0.f);

    int start = ptrA[w], end = ptrA[w + 1];
    for (int i = start; i < end; i += 32) {
        int take = min(32, end - i);
        if (lane < take) se[wl][lane] = eA[i + lane];
        __syncwarp();
        if (take == 32) {
            #pragma unroll 8
            for (int j = 0; j < 32; ++j) gather_fma(acc, se[wl][j], XuA, lane);
        } else {
            for (int j = 0; j < take; ++j) gather_fma(acc, se[wl][j], XuA, lane);
        }
        __syncwarp();
    }
    start = ptrB[w]; end = ptrB[w + 1];
    for (int i = start; i < end; i += 32) {
        int take = min(32, end - i);
        if (lane < take) se[wl][lane] = eB[i + lane];
        __syncwarp();
        for (int j = 0; j < take; ++j) gather_fma(acc, se[wl][j], XuB, lane);
        __syncwarp();
    }
    acc.x = sigf(acc.x); acc.y = sigf(acc.y); acc.z = sigf(acc.z); acc.w = sigf(acc.w);
    out[(size_t)w * 32 + lane] = acc;
}

// ---------------- host ----------------
static void build_csr(const int* rows, const int* cols, const float* vals, int nnz,
                      int n, int* cnt, int* ptr, int* work, int* sums, int2* e)
{
    cudaMemsetAsync(cnt, 0, (size_t)n * sizeof(int));
    hist_kernel<<<(nnz + 255) / 256, 256>>>(rows, nnz, cnt);
    int nB = (n + 4095) / 4096;
    scan_chunk<<<nB, 1024>>>(cnt, ptr, sums, n);
    scan_sums<<<1, 64>>>(sums, nB);
    add_base_work<<<(n + 256) / 256, 256>>>(ptr, work, sums, n, nnz);
    scatter_kernel<<<(nnz + 255) / 256, 256>>>(rows, cols, vals, nnz, work, e);
}

extern "C" void kernel_launch(void* const* d_in, const int* in_sizes, int n_in,
                              void* d_out, int out_size)
{
    const float* x        = (const float*)d_in[0];
    const float* W1_00    = (const float*)d_in[1];
    const float* W1_01    = (const float*)d_in[2];
    const float* W2_00    = (const float*)d_in[3];
    const float* W2_10    = (const float*)d_in[4];
    const int*   adj_rows = (const int*)  d_in[5];
    const int*   adj_cols = (const int*)  d_in[6];
    const float* adj_vals = (const float*)d_in[7];
    const int*   inc_rows = (const int*)  d_in[8];
    const int*   inc_cols = (const int*)  d_in[9];
    const float* inc_vals = (const float*)d_in[10];
    const int adj_nnz = in_sizes[5];
    const int inc_nnz = in_sizes[8];
    const int nodes   = in_sizes[0] / CDIM;   // 100000
    const int edges   = NEDGES;               // 200000

    __half *hx, *hB, *hC, *hX, *hY, *hW;
    int *adj_ptr, *it_ptr, *in_ptr, *cnt, *work, *sums;
    int2 *adj_e, *it_e, *in_e;
    cudaGetSymbolAddress((void**)&hx, g_hx);
    cudaGetSymbolAddress((void**)&hB, g_hB);
    cudaGetSymbolAddress((void**)&hC, g_hC);
    cudaGetSymbolAddress((void**)&hX, g_hX);
    cudaGetSymbolAddress((void**)&hY, g_hY);
    cudaGetSymbolAddress((void**)&hW, g_hW);
    cudaGetSymbolAddress((void**)&adj_ptr, g_adj_ptr);
    cudaGetSymbolAddress((void**)&adj_e,   g_adj_e);
    cudaGetSymbolAddress((void**)&it_ptr,  g_it_ptr);
    cudaGetSymbolAddress((void**)&it_e,    g_it_e);
    cudaGetSymbolAddress((void**)&in_ptr,  g_in_ptr);
    cudaGetSymbolAddress((void**)&in_e,    g_in_e);
    cudaGetSymbolAddress((void**)&cnt,  g_cnt);
    cudaGetSymbolAddress((void**)&work, g_work);
    cudaGetSymbolAddress((void**)&sums, g_sums);

    __half* hW0 = hW;
    __half* hW1 = hW + CDIM * CDIM;
    __half* hW2 = hW + 2 * CDIM * CDIM;
    __half* hW3 = hW + 3 * CDIM * CDIM;

    const int SMEM = 128 * LDH * 2 * 2;   // 69632 bytes
    cudaFuncSetAttribute(gemm_tc, cudaFuncAttributeMaxDynamicSharedMemorySize, SMEM);

    // fp16 converts (x once; 4 weights)
    int xN4 = nodes * CDIM / 4;
    f2h_kernel<<<(xN4 + 255) / 256, 256>>>((const float4*)x, (uint2*)hx, xN4);
    int wN4 = CDIM * CDIM / 4;
    f2h_kernel<<<(wN4 + 255) / 256, 256>>>((const float4*)W1_00, (uint2*)hW0, wN4);
    f2h_kernel<<<(wN4 + 255) / 256, 256>>>((const float4*)W1_01, (uint2*)hW1, wN4);
    f2h_kernel<<<(wN4 + 255) / 256, 256>>>((const float4*)W2_00, (uint2*)hW2, wN4);
    f2h_kernel<<<(wN4 + 255) / 256, 256>>>((const float4*)W2_10, (uint2*)hW3, wN4);

    // CSR builds
    build_csr(adj_rows, adj_cols, adj_vals, adj_nnz, nodes, cnt, adj_ptr, work, sums, adj_e);
    build_csr(inc_cols, inc_rows, inc_vals, inc_nnz, edges, cnt, it_ptr,  work, sums, it_e);
    build_csr(inc_rows, inc_cols, inc_vals, inc_nnz, nodes, cnt, in_ptr,  work, sums, in_e);

    // Level 1
    gemm_tc<<<(nodes + 127) / 128, 256, SMEM>>>(hx, hW0, hX, nodes);
    spmm_h<<<(nodes + 7) / 8, 256>>>(adj_ptr, adj_e, hX, hB, nodes);
    gemm_tc<<<(nodes + 127) / 128, 256, SMEM>>>(hx, hW1, hX, nodes);
    spmm_h<<<(edges + 7) / 8, 256>>>(it_ptr, it_e, hX, hC, edges);
    // Level 2
    gemm_tc<<<(nodes + 127) / 128, 256, SMEM>>>(hB, hW2, hY, nodes);
    gemm_tc<<<(edges + 127) / 128, 256, SMEM>>>(hC, hW3, hX, edges);
    // Merge + sigmoid
    spmm_dual_h<<<(nodes + 7) / 8, 256>>>(adj_ptr, adj_e, hY,
                                          in_ptr, in_e, hX,
                                          (float4*)d_out, nodes);
}

// round 5
// speedup vs baseline: 3.1828x; 1.1257x over previous
#include <cuda_runtime.h>
#include <cuda_fp16.h>
#include <mma.h>
#include <cstdint>

#define CDIM    128
#define NNODES  100000
#define NEDGES  200000
#define ADJ_MAX 3200000
#define INC_MAX 400000
#define NTOT    (NNODES + NEDGES + NNODES)        // 400000 concatenated rows
#define E_MAX   (ADJ_MAX + 2 * INC_MAX)           // 4.0M concatenated edges
#define LDH     136

using namespace nvcuda;

// ---------------- scratch (__device__ globals: allocation-free) ----------------
__device__ __align__(128) __half g_hx [(size_t)NNODES * CDIM];   // x (fp16)
__device__ __align__(128) __half g_h1 [(size_t)NNODES * CDIM];   // h1
__device__ __align__(128) __half g_h2 [(size_t)NNODES * CDIM];   // h2
__device__ __align__(128) __half g_h4 [(size_t)NEDGES * CDIM];   // h4
__device__ __align__(128) __half g_hY [(size_t)NNODES * CDIM];   // h3
__device__ __align__(128) __half g_hB [(size_t)NNODES * CDIM];   // nodes_l1
__device__ __align__(128) __half g_hC [(size_t)NEDGES * CDIM];   // edges_l1
__device__ __align__(128) __half g_hW [4][CDIM * CDIM];          // weights

// unified CSR over concatenated row space
__device__ int  g_cnt [NTOT];
__device__ int  g_ptr [NTOT + 1];
__device__ int  g_work[NTOT];
__device__ int2 g_e   [E_MAX];
__device__ int  g_sums[128];

__device__ __forceinline__ float sigf(float x) { return 1.f / (1.f + __expf(-x)); }
__device__ __forceinline__ unsigned h2u(__half2 h) { return *reinterpret_cast<unsigned*>(&h); }

// ---------------- converts ----------------
__global__ __launch_bounds__(256) void f2h_kernel(const float4* __restrict__ in,
                                                  uint2* __restrict__ out, int n4)
{
    int i = blockIdx.x * blockDim.x + threadIdx.x;
    if (i < n4) {
        float4 v = in[i];
        out[i] = make_uint2(h2u(__floats2half2_rn(v.x, v.y)),
                            h2u(__floats2half2_rn(v.z, v.w)));
    }
}

// all 4 weights in one launch (4 x 4096 float4)
__global__ __launch_bounds__(256) void f2h_w4(const float4* __restrict__ a,
                                              const float4* __restrict__ b,
                                              const float4* __restrict__ c,
                                              const float4* __restrict__ d,
                                              uint2* __restrict__ out)
{
    int i = blockIdx.x * blockDim.x + threadIdx.x;   // 0..16383
    const float4* src = (i < 4096) ? a : (i < 8192) ? b : (i < 12288) ? c : d;
    float4 v = src[i & 4095];
    out[i] = make_uint2(h2u(__floats2half2_rn(v.x, v.y)),
                        h2u(__floats2half2_rn(v.z, v.w)));
}

// ---------------- tensor-core GEMM: outH[M,128] = half( A[M,128] @ W[128,128] ) ------
__global__ __launch_bounds__(256, 1) void gemm_tc(const __half* __restrict__ A,
                                                  const __half* __restrict__ W,
                                                  __half* __restrict__ out, int M)
{
    extern __shared__ char smem[];
    __half* sA = reinterpret_cast<__half*>(smem);
    __half* sW = reinterpret_cast<__half*>(smem + 128 * LDH * 2);
    float*  sO = reinterpret_cast<float*>(smem);

    const int tid  = threadIdx.x;
    const int row0 = blockIdx.x * 128;

    #pragma unroll
    for (int i = 0; i < 8; ++i) {
        int e = tid + i * 256;
        int r = e >> 4, c = e & 15;
        uint4 v = reinterpret_cast<const uint4*>(W)[e];
        *reinterpret_cast<uint4*>(&sW[r * LDH + c * 8]) = v;
    }
    #pragma unroll
    for (int i = 0; i < 8; ++i) {
        int e = tid + i * 256;
        int r = e >> 4, c = e & 15;
        uint4 v = make_uint4(0u, 0u, 0u, 0u);
        if (row0 + r < M) v = reinterpret_cast<const uint4*>(A)[(size_t)(row0 + r) * 16 + c];
        *reinterpret_cast<uint4*>(&sA[r * LDH + c * 8]) = v;
    }
    __syncthreads();

    const int warpId = tid >> 5;
    const int wr = warpId >> 1;
    const int wc = warpId & 1;

    wmma::fragment<wmma::accumulator, 16, 16, 16, float> c[2][4];
    #pragma unroll
    for (int i = 0; i < 2; ++i)
        #pragma unroll
        for (int j = 0; j < 4; ++j) wmma::fill_fragment(c[i][j], 0.f);

    #pragma unroll
    for (int k = 0; k < 8; ++k) {
        wmma::fragment<wmma::matrix_a, 16, 16, 16, __half, wmma::row_major> a[2];
        wmma::fragment<wmma::matrix_b, 16, 16, 16, __half, wmma::row_major> b[4];
        #pragma unroll
        for (int i = 0; i < 2; ++i)
            wmma::load_matrix_sync(a[i], &sA[(wr * 32 + i * 16) * LDH + k * 16], LDH);
        #pragma unroll
        for (int j = 0; j < 4; ++j)
            wmma::load_matrix_sync(b[j], &sW[(k * 16) * LDH + wc * 64 + j * 16], LDH);
        #pragma unroll
        for (int i = 0; i < 2; ++i)
            #pragma unroll
            for (int j = 0; j < 4; ++j)
                wmma::mma_sync(c[i][j], a[i], b[j], c[i][j]);
    }

    __syncthreads();
    #pragma unroll
    for (int i = 0; i < 2; ++i)
        #pragma unroll
        for (int j = 0; j < 4; ++j)
            wmma::store_matrix_sync(&sO[(wr * 32 + i * 16) * 128 + wc * 64 + j * 16],
                                    c[i][j], 128, wmma::mem_row_major);
    __syncthreads();

    #pragma unroll
    for (int i = 0; i < 16; ++i) {
        int e  = tid + i * 256;
        int r  = e >> 5, c4 = e & 31;
        int grow = row0 + r;
        if (grow < M) {
            float4 v = reinterpret_cast<float4*>(sO)[(size_t)r * 32 + c4];
            uint2 o = make_uint2(h2u(__floats2half2_rn(v.x, v.y)),
                                 h2u(__floats2half2_rn(v.z, v.w)));
            reinterpret_cast<uint2*>(out)[(size_t)grow * 32 + c4] = o;
        }
    }
}

// ---------------- unified CSR build (all 3 matrices, concatenated row space) --------
__global__ __launch_bounds__(256) void hist_all(const int* __restrict__ adj_rows, int adj_nnz,
                                                const int* __restrict__ inc_rows,
                                                const int* __restrict__ inc_cols, int inc_nnz,
                                                int* __restrict__ cnt)
{
    int i = blockIdx.x * blockDim.x + threadIdx.x;
    if (i < adj_nnz) atomicAdd(&cnt[adj_rows[i]], 1);
    if (i < inc_nnz) {
        atomicAdd(&cnt[NNODES + inc_cols[i]], 1);            // incT rows = edge ids
        atomicAdd(&cnt[NNODES + NEDGES + inc_rows[i]], 1);   // inc rows = node ids
    }
}

__global__ __launch_bounds__(1024) void scan_chunk(const int* __restrict__ in,
                                                   int* __restrict__ out,
                                                   int* __restrict__ sums, int n)
{
    __shared__ int sh[1024];
    int t = threadIdx.x;
    int idx = blockIdx.x * 4096 + t * 4;
    int a0 = (idx     < n) ? in[idx]     : 0;
    int a1 = (idx + 1 < n) ? in[idx + 1] : 0;
    int a2 = (idx + 2 < n) ? in[idx + 2] : 0;
    int a3 = (idx + 3 < n) ? in[idx + 3] : 0;
    int s = a0 + a1 + a2 + a3;
    sh[t] = s;
    __syncthreads();
    for (int off = 1; off < 1024; off <<= 1) {
        int v = (t >= off) ? sh[t - off] : 0;
        __syncthreads();
        sh[t] += v;
        __syncthreads();
    }
    int excl = sh[t] - s;
    if (idx     < n) out[idx]     = excl;
    if (idx + 1 < n) out[idx + 1] = excl + a0;
    if (idx + 2 < n) out[idx + 2] = excl + a0 + a1;
    if (idx + 3 < n) out[idx + 3] = excl + a0 + a1 + a2;
    if (t == 1023) sums[blockIdx.x] = sh[1023];
}

__global__ __launch_bounds__(128) void scan_sums(int* __restrict__ sums, int nB)
{
    __shared__ int sh[128];
    int t = threadIdx.x;
    int v = (t < nB) ? sums[t] : 0;
    sh[t] = v;
    __syncthreads();
    for (int off = 1; off < 128; off <<= 1) {
        int u = (t >= off) ? sh[t - off] : 0;
        __syncthreads();
        sh[t] += u;
        __syncthreads();
    }
    if (t < nB) sums[t] = sh[t] - v;
}

__global__ __launch_bounds__(256) void add_base_work(int* __restrict__ ptr,
                                                     int* __restrict__ work,
                                                     const int* __restrict__ sums,
                                                     int n, int nnz_total)
{
    int i = blockIdx.x * blockDim.x + threadIdx.x;
    if (i < n) {
        int v = ptr[i] + sums[i >> 12];
        ptr[i]  = v;
        work[i] = v;
    }
    if (i == 0) ptr[n] = nnz_total;
}

__global__ __launch_bounds__(256) void scatter_all(const int* __restrict__ adj_rows,
                                                   const int* __restrict__ adj_cols,
                                                   const float* __restrict__ adj_vals, int adj_nnz,
                                                   const int* __restrict__ inc_rows,
                                                   const int* __restrict__ inc_cols,
                                                   const float* __restrict__ inc_vals, int inc_nnz,
                                                   int* __restrict__ work,
                                                   int2* __restrict__ e)
{
    int i = blockIdx.x * blockDim.x + threadIdx.x;
    if (i < adj_nnz) {
        int p = atomicAdd(&work[adj_rows[i]], 1);
        e[p] = make_int2(adj_cols[i], __float_as_int(adj_vals[i]));
    }
    if (i < inc_nnz) {
        int vv = __float_as_int(inc_vals[i]);
        int p = atomicAdd(&work[NNODES + inc_cols[i]], 1);
        e[p] = make_int2(inc_rows[i], vv);
        int q = atomicAdd(&work[NNODES + NEDGES + inc_rows[i]], 1);
        e[q] = make_int2(inc_cols[i], vv);
    }
}

// ---------------- CSR SpMM (fp16 features): warp per row ----------------
__device__ __forceinline__ void gather_fma(float4& acc, int2 t,
                                           const uint2* __restrict__ Xu, int lane)
{
    float v  = __int_as_float(t.y);
    uint2 u  = __ldg(&Xu[(size_t)t.x * 32 + lane]);
    float2 f0 = __half22float2(*reinterpret_cast<__half2*>(&u.x));
    float2 f1 = __half22float2(*reinterpret_cast<__half2*>(&u.y));
    acc.x += v * f0.x; acc.y += v * f0.y; acc.z += v * f1.x; acc.w += v * f1.y;
}

// out (fp16) = sigmoid(CSR @ X)
__global__ __launch_bounds__(256) void spmm_h(const int* __restrict__ ptr,
                                              const int2* __restrict__ e,
                                              const __half* __restrict__ X,
                                              __half* __restrict__ out, int nrows)
{
    __shared__ int2 se[8][32];
    int w    = (blockIdx.x * blockDim.x + threadIdx.x) >> 5;
    int lane = threadIdx.x & 31;
    int wl   = threadIdx.x >> 5;
    if (w >= nrows) return;
    const uint2* Xu = reinterpret_cast<const uint2*>(X);
    int start = ptr[w], end = ptr[w + 1];
    float4 acc = make_float4(0.f, 0.f, 0.f, 0.f);
    for (int i = start; i < end; i += 32) {
        int take = min(32, end - i);
        if (lane < take) se[wl][lane] = e[i + lane];
        __syncwarp();
        if (take == 32) {
            #pragma unroll 8
            for (int j = 0; j < 32; ++j) gather_fma(acc, se[wl][j], Xu, lane);
        } else {
            for (int j = 0; j < take; ++j) gather_fma(acc, se[wl][j], Xu, lane);
        }
        __syncwarp();
    }
    uint2 o = make_uint2(h2u(__floats2half2_rn(sigf(acc.x), sigf(acc.y))),
                         h2u(__floats2half2_rn(sigf(acc.z), sigf(acc.w))));
    reinterpret_cast<uint2*>(out)[(size_t)w * 32 + lane] = o;
}

// out (fp32) = sigmoid(adjCSR @ XA + incCSR @ XB)
__global__ __launch_bounds__(256) void spmm_dual_h(const int* __restrict__ ptrA,
                                                   const __half* __restrict__ XA,
                                                   const int* __restrict__ ptrB,
                                                   const __half* __restrict__ XB,
                                                   const int2* __restrict__ e,
                                                   float4* __restrict__ out, int nrows)
{
    __shared__ int2 se[8][32];
    int w    = (blockIdx.x * blockDim.x + threadIdx.x) >> 5;
    int lane = threadIdx.x & 31;
    int wl   = threadIdx.x >> 5;
    if (w >= nrows) return;
    const uint2* XuA = reinterpret_cast<const uint2*>(XA);
    const uint2* XuB = reinterpret_cast<const uint2*>(XB);
    float4 acc = make_float4(0.f, 0.f, 0.f, 0.f);

    int start = ptrA[w], end = ptrA[w + 1];
    for (int i = start; i < end; i += 32) {
        int take = min(32, end - i);
        if (lane < take) se[wl][lane] = e[i + lane];
        __syncwarp();
        if (take == 32) {
            #pragma unroll 8
            for (int j = 0; j < 32; ++j) gather_fma(acc, se[wl][j], XuA, lane);
        } else {
            for (int j = 0; j < take; ++j) gather_fma(acc, se[wl][j], XuA, lane);
        }
        __syncwarp();
    }
    start = ptrB[w]; end = ptrB[w + 1];
    for (int i = start; i < end; i += 32) {
        int take = min(32, end - i);
        if (lane < take) se[wl][lane] = e[i + lane];
        __syncwarp();
        for (int j = 0; j < take; ++j) gather_fma(acc, se[wl][j], XuB, lane);
        __syncwarp();
    }
    acc.x = sigf(acc.x); acc.y = sigf(acc.y); acc.z = sigf(acc.z); acc.w = sigf(acc.w);
    out[(size_t)w * 32 + lane] = acc;
}

// ---------------- host ----------------
extern "C" void kernel_launch(void* const* d_in, const int* in_sizes, int n_in,
                              void* d_out, int out_size)
{
    const float* x        = (const float*)d_in[0];
    const float* W1_00    = (const float*)d_in[1];
    const float* W1_01    = (const float*)d_in[2];
    const float* W2_00    = (const float*)d_in[3];
    const float* W2_10    = (const float*)d_in[4];
    const int*   adj_rows = (const int*)  d_in[5];
    const int*   adj_cols = (const int*)  d_in[6];
    const float* adj_vals = (const float*)d_in[7];
    const int*   inc_rows = (const int*)  d_in[8];
    const int*   inc_cols = (const int*)  d_in[9];
    const float* inc_vals = (const float*)d_in[10];
    const int adj_nnz = in_sizes[5];
    const int inc_nnz = in_sizes[8];
    const int nodes   = NNODES;
    const int edges   = NEDGES;
    const int nnz_tot = adj_nnz + 2 * inc_nnz;

    __half *hx, *h1, *h2, *h4, *hY, *hB, *hC, *hW;
    int *cnt, *ptr, *work, *sums;
    int2 *eAll;
    cudaGetSymbolAddress((void**)&hx, g_hx);
    cudaGetSymbolAddress((void**)&h1, g_h1);
    cudaGetSymbolAddress((void**)&h2, g_h2);
    cudaGetSymbolAddress((void**)&h4, g_h4);
    cudaGetSymbolAddress((void**)&hY, g_hY);
    cudaGetSymbolAddress((void**)&hB, g_hB);
    cudaGetSymbolAddress((void**)&hC, g_hC);
    cudaGetSymbolAddress((void**)&hW, g_hW);
    cudaGetSymbolAddress((void**)&cnt,  g_cnt);
    cudaGetSymbolAddress((void**)&ptr,  g_ptr);
    cudaGetSymbolAddress((void**)&work, g_work);
    cudaGetSymbolAddress((void**)&sums, g_sums);
    cudaGetSymbolAddress((void**)&eAll, g_e);

    __half* hW0 = hW;
    __half* hW1 = hW + CDIM * CDIM;
    __half* hW2 = hW + 2 * CDIM * CDIM;
    __half* hW3 = hW + 3 * CDIM * CDIM;

    static cudaStream_t s1 = nullptr;
    static cudaEvent_t evFork = nullptr, evG1 = nullptr, evBuild = nullptr, evJoin = nullptr;
    if (!s1) {
        cudaStreamCreateWithFlags(&s1, cudaStreamNonBlocking);
        cudaEventCreateWithFlags(&evFork,  cudaEventDisableTiming);
        cudaEventCreateWithFlags(&evG1,    cudaEventDisableTiming);
        cudaEventCreateWithFlags(&evBuild, cudaEventDisableTiming);
        cudaEventCreateWithFlags(&evJoin,  cudaEventDisableTiming);
        cudaFuncSetAttribute(gemm_tc, cudaFuncAttributeMaxDynamicSharedMemorySize,
                             128 * LDH * 2 * 2);
    }
    const int SMEM = 128 * LDH * 2 * 2;

    // ---- fork ----
    cudaEventRecord(evFork, 0);
    cudaStreamWaitEvent(s1, evFork, 0);

    // ---- stream s1: converts + level-1 GEMMs ----
    int xN4 = nodes * CDIM / 4;
    f2h_kernel<<<(xN4 + 255) / 256, 256, 0, s1>>>((const float4*)x, (uint2*)hx, xN4);
    f2h_w4<<<(4 * 4096 + 255) / 256, 256, 0, s1>>>((const float4*)W1_00, (const float4*)W1_01,
                                                   (const float4*)W2_00, (const float4*)W2_10,
                                                   (uint2*)hW0);
    gemm_tc<<<(nodes + 127) / 128, 256, SMEM, s1>>>(hx, hW0, h1, nodes);
    cudaEventRecord(evG1, s1);
    gemm_tc<<<(nodes + 127) / 128, 256, SMEM, s1>>>(hx, hW1, h2, nodes);

    // ---- stream 0: unified CSR build ----
    cudaMemsetAsync(cnt, 0, (size_t)NTOT * sizeof(int), 0);
    {
        int mx = max(adj_nnz, inc_nnz);
        hist_all<<<(mx + 255) / 256, 256>>>(adj_rows, adj_nnz, inc_rows, inc_cols, inc_nnz, cnt);
        int nB = (NTOT + 4095) / 4096;
        scan_chunk<<<nB, 1024>>>(cnt, ptr, sums, NTOT);
        scan_sums<<<1, 128>>>(sums, nB);
        add_base_work<<<(NTOT + 255) / 256, 256>>>(ptr, work, sums, NTOT, nnz_tot);
        scatter_all<<<(mx + 255) / 256, 256>>>(adj_rows, adj_cols, adj_vals, adj_nnz,
                                               inc_rows, inc_cols, inc_vals, inc_nnz,
                                               work, eAll);
    }
    cudaEventRecord(evBuild, 0);

    // ---- stream 0: node branch (S1 -> G3) ----
    cudaStreamWaitEvent(0, evG1, 0);
    spmm_h<<<(nodes + 7) / 8, 256>>>(ptr, eAll, h1, hB, nodes);               // adj rows [0,N)
    gemm_tc<<<(nodes + 127) / 128, 256, SMEM>>>(hB, hW2, hY, nodes);

    // ---- stream s1: edge branch (S2 -> G4) ----
    cudaStreamWaitEvent(s1, evBuild, 0);
    spmm_h<<<(edges + 7) / 8, 256, 0, s1>>>(ptr + nodes, eAll, h2, hC, edges); // incT rows
    gemm_tc<<<(edges + 127) / 128, 256, SMEM, s1>>>(hC, hW3, h4, edges);
    cudaEventRecord(evJoin, s1);

    // ---- join + merge ----
    cudaStreamWaitEvent(0, evJoin, 0);
    spmm_dual_h<<<(nodes + 7) / 8, 256>>>(ptr, hY,
                                          ptr + nodes + edges, h4,
                                          eAll, (float4*)d_out, nodes);
}

// round 6
// speedup vs baseline: 3.2734x; 1.0285x over previous
#include <cuda_runtime.h>
#include <cuda_fp16.h>
#include <mma.h>
#include <cstdint>

#define CDIM    128
#define NNODES  100000
#define NEDGES  200000
#define ADJ_MAX 3200000
#define INC_MAX 400000
#define NTOT    (NNODES + NEDGES + NNODES)        // 400000 concatenated rows
#define E_MAX   (ADJ_MAX + 2 * INC_MAX)           // 4.0M concatenated edges
#define LDH     136

using namespace nvcuda;

// ---------------- scratch (__device__ globals: allocation-free) ----------------
__device__ __align__(128) __half g_hx [(size_t)NNODES * CDIM];   // x (fp16)
__device__ __align__(128) __half g_h1 [(size_t)NNODES * CDIM];   // h1
__device__ __align__(128) __half g_h2 [(size_t)NNODES * CDIM];   // h2
__device__ __align__(128) __half g_h4 [(size_t)NEDGES * CDIM];   // h4
__device__ __align__(128) __half g_hY [(size_t)NNODES * CDIM];   // h3
__device__ __align__(128) __half g_hB [(size_t)NNODES * CDIM];   // nodes_l1
__device__ __align__(128) __half g_hC [(size_t)NEDGES * CDIM];   // edges_l1
__device__ __align__(128) __half g_hW [4][CDIM * CDIM];          // weights
__device__ __align__(128) float  g_pf [(size_t)NNODES * CDIM];   // inc partial (fp32)

// unified CSR over concatenated row space
__device__ int  g_cnt [NTOT];
__device__ int  g_ptr [NTOT + 1];
__device__ int  g_work[NTOT];
__device__ int2 g_e   [E_MAX];
__device__ int  g_sums[128];

__device__ __forceinline__ float sigf(float x) { return 1.f / (1.f + __expf(-x)); }
__device__ __forceinline__ unsigned h2u(__half2 h) { return *reinterpret_cast<unsigned*>(&h); }

// ---------------- converts ----------------
__global__ __launch_bounds__(256) void f2h_kernel(const float4* __restrict__ in,
                                                  uint2* __restrict__ out, int n4)
{
    int i = blockIdx.x * blockDim.x + threadIdx.x;
    if (i < n4) {
        float4 v = in[i];
        out[i] = make_uint2(h2u(__floats2half2_rn(v.x, v.y)),
                            h2u(__floats2half2_rn(v.z, v.w)));
    }
}

__global__ __launch_bounds__(256) void f2h_w4(const float4* __restrict__ a,
                                              const float4* __restrict__ b,
                                              const float4* __restrict__ c,
                                              const float4* __restrict__ d,
                                              uint2* __restrict__ out)
{
    int i = blockIdx.x * blockDim.x + threadIdx.x;   // 0..16383
    const float4* src = (i < 4096) ? a : (i < 8192) ? b : (i < 12288) ? c : d;
    float4 v = src[i & 4095];
    out[i] = make_uint2(h2u(__floats2half2_rn(v.x, v.y)),
                        h2u(__floats2half2_rn(v.z, v.w)));
}

// ---------------- tensor-core GEMM: outH[M,128] = half( A[M,128] @ W[128,128] ) ------
// launch_bounds(256,2): cap regs at 128 so 2 CTAs/SM are resident (occ fix).
__global__ __launch_bounds__(256, 2) void gemm_tc(const __half* __restrict__ A,
                                                  const __half* __restrict__ W,
                                                  __half* __restrict__ out, int M)
{
    extern __shared__ char smem[];
    __half* sA = reinterpret_cast<__half*>(smem);
    __half* sW = reinterpret_cast<__half*>(smem + 128 * LDH * 2);
    float*  sO = reinterpret_cast<float*>(smem);

    const int tid  = threadIdx.x;
    const int row0 = blockIdx.x * 128;

    #pragma unroll
    for (int i = 0; i < 8; ++i) {
        int e = tid + i * 256;
        int r = e >> 4, c = e & 15;
        uint4 v = reinterpret_cast<const uint4*>(W)[e];
        *reinterpret_cast<uint4*>(&sW[r * LDH + c * 8]) = v;
    }
    #pragma unroll
    for (int i = 0; i < 8; ++i) {
        int e = tid + i * 256;
        int r = e >> 4, c = e & 15;
        uint4 v = make_uint4(0u, 0u, 0u, 0u);
        if (row0 + r < M) v = reinterpret_cast<const uint4*>(A)[(size_t)(row0 + r) * 16 + c];
        *reinterpret_cast<uint4*>(&sA[r * LDH + c * 8]) = v;
    }
    __syncthreads();

    const int warpId = tid >> 5;
    const int wr = warpId >> 1;
    const int wc = warpId & 1;

    wmma::fragment<wmma::accumulator, 16, 16, 16, float> c[2][4];
    #pragma unroll
    for (int i = 0; i < 2; ++i)
        #pragma unroll
        for (int j = 0; j < 4; ++j) wmma::fill_fragment(c[i][j], 0.f);

    #pragma unroll
    for (int k = 0; k < 8; ++k) {
        wmma::fragment<wmma::matrix_a, 16, 16, 16, __half, wmma::row_major> a[2];
        wmma::fragment<wmma::matrix_b, 16, 16, 16, __half, wmma::row_major> b[4];
        #pragma unroll
        for (int i = 0; i < 2; ++i)
            wmma::load_matrix_sync(a[i], &sA[(wr * 32 + i * 16) * LDH + k * 16], LDH);
        #pragma unroll
        for (int j = 0; j < 4; ++j)
            wmma::load_matrix_sync(b[j], &sW[(k * 16) * LDH + wc * 64 + j * 16], LDH);
        #pragma unroll
        for (int i = 0; i < 2; ++i)
            #pragma unroll
            for (int j = 0; j < 4; ++j)
                wmma::mma_sync(c[i][j], a[i], b[j], c[i][j]);
    }

    __syncthreads();
    #pragma unroll
    for (int i = 0; i < 2; ++i)
        #pragma unroll
        for (int j = 0; j < 4; ++j)
            wmma::store_matrix_sync(&sO[(wr * 32 + i * 16) * 128 + wc * 64 + j * 16],
                                    c[i][j], 128, wmma::mem_row_major);
    __syncthreads();

    #pragma unroll
    for (int i = 0; i < 16; ++i) {
        int e  = tid + i * 256;
        int r  = e >> 5, c4 = e & 31;
        int grow = row0 + r;
        if (grow < M) {
            float4 v = reinterpret_cast<float4*>(sO)[(size_t)r * 32 + c4];
            uint2 o = make_uint2(h2u(__floats2half2_rn(v.x, v.y)),
                                 h2u(__floats2half2_rn(v.z, v.w)));
            reinterpret_cast<uint2*>(out)[(size_t)grow * 32 + c4] = o;
        }
    }
}

// ---------------- unified CSR build ----------------
__global__ __launch_bounds__(256) void hist_all(const int* __restrict__ adj_rows, int adj_nnz,
                                                const int* __restrict__ inc_rows,
                                                const int* __restrict__ inc_cols, int inc_nnz,
                                                int* __restrict__ cnt)
{
    int i = blockIdx.x * blockDim.x + threadIdx.x;
    if (i < adj_nnz) atomicAdd(&cnt[adj_rows[i]], 1);
    if (i < inc_nnz) {
        atomicAdd(&cnt[NNODES + inc_cols[i]], 1);
        atomicAdd(&cnt[NNODES + NEDGES + inc_rows[i]], 1);
    }
}

__global__ __launch_bounds__(1024) void scan_chunk(const int* __restrict__ in,
                                                   int* __restrict__ out,
                                                   int* __restrict__ sums, int n)
{
    __shared__ int sh[1024];
    int t = threadIdx.x;
    int idx = blockIdx.x * 4096 + t * 4;
    int a0 = (idx     < n) ? in[idx]     : 0;
    int a1 = (idx + 1 < n) ? in[idx + 1] : 0;
    int a2 = (idx + 2 < n) ? in[idx + 2] : 0;
    int a3 = (idx + 3 < n) ? in[idx + 3] : 0;
    int s = a0 + a1 + a2 + a3;
    sh[t] = s;
    __syncthreads();
    for (int off = 1; off < 1024; off <<= 1) {
        int v = (t >= off) ? sh[t - off] : 0;
        __syncthreads();
        sh[t] += v;
        __syncthreads();
    }
    int excl = sh[t] - s;
    if (idx     < n) out[idx]     = excl;
    if (idx + 1 < n) out[idx + 1] = excl + a0;
    if (idx + 2 < n) out[idx + 2] = excl + a0 + a1;
    if (idx + 3 < n) out[idx + 3] = excl + a0 + a1 + a2;
    if (t == 1023) sums[blockIdx.x] = sh[1023];
}

__global__ __launch_bounds__(128) void scan_sums(int* __restrict__ sums, int nB)
{
    __shared__ int sh[128];
    int t = threadIdx.x;
    int v = (t < nB) ? sums[t] : 0;
    sh[t] = v;
    __syncthreads();
    for (int off = 1; off < 128; off <<= 1) {
        int u = (t >= off) ? sh[t - off] : 0;
        __syncthreads();
        sh[t] += u;
        __syncthreads();
    }
    if (t < nB) sums[t] = sh[t] - v;
}

__global__ __launch_bounds__(256) void add_base_work(int* __restrict__ ptr,
                                                     int* __restrict__ work,
                                                     const int* __restrict__ sums,
                                                     int n, int nnz_total)
{
    int i = blockIdx.x * blockDim.x + threadIdx.x;
    if (i < n) {
        int v = ptr[i] + sums[i >> 12];
        ptr[i]  = v;
        work[i] = v;
    }
    if (i == 0) ptr[n] = nnz_total;
}

__global__ __launch_bounds__(256) void scatter_all(const int* __restrict__ adj_rows,
                                                   const int* __restrict__ adj_cols,
                                                   const float* __restrict__ adj_vals, int adj_nnz,
                                                   const int* __restrict__ inc_rows,
                                                   const int* __restrict__ inc_cols,
                                                   const float* __restrict__ inc_vals, int inc_nnz,
                                                   int* __restrict__ work,
                                                   int2* __restrict__ e)
{
    int i = blockIdx.x * blockDim.x + threadIdx.x;
    if (i < adj_nnz) {
        int p = atomicAdd(&work[adj_rows[i]], 1);
        e[p] = make_int2(adj_cols[i], __float_as_int(adj_vals[i]));
    }
    if (i < inc_nnz) {
        int vv = __float_as_int(inc_vals[i]);
        int p = atomicAdd(&work[NNODES + inc_cols[i]], 1);
        e[p] = make_int2(inc_rows[i], vv);
        int q = atomicAdd(&work[NNODES + NEDGES + inc_rows[i]], 1);
        e[q] = make_int2(inc_cols[i], vv);
    }
}

// ---------------- CSR SpMM (fp16 features): warp per row ----------------
__device__ __forceinline__ void gather_fma(float4& acc, int2 t,
                                           const uint2* __restrict__ Xu, int lane)
{
    float v  = __int_as_float(t.y);
    uint2 u  = __ldg(&Xu[(size_t)t.x * 32 + lane]);
    float2 f0 = __half22float2(*reinterpret_cast<__half2*>(&u.x));
    float2 f1 = __half22float2(*reinterpret_cast<__half2*>(&u.y));
    acc.x += v * f0.x; acc.y += v * f0.y; acc.z += v * f1.x; acc.w += v * f1.y;
}

// out (fp16) = sigmoid(CSR @ X)
__global__ __launch_bounds__(256) void spmm_h(const int* __restrict__ ptr,
                                              const int2* __restrict__ e,
                                              const __half* __restrict__ X,
                                              __half* __restrict__ out, int nrows)
{
    __shared__ int2 se[8][32];
    int w    = (blockIdx.x * blockDim.x + threadIdx.x) >> 5;
    int lane = threadIdx.x & 31;
    int wl   = threadIdx.x >> 5;
    if (w >= nrows) return;
    const uint2* Xu = reinterpret_cast<const uint2*>(X);
    int start = ptr[w], end = ptr[w + 1];
    float4 acc = make_float4(0.f, 0.f, 0.f, 0.f);
    for (int i = start; i < end; i += 32) {
        int take = min(32, end - i);
        if (lane < take) se[wl][lane] = e[i + lane];
        __syncwarp();
        if (take == 32) {
            #pragma unroll 8
            for (int j = 0; j < 32; ++j) gather_fma(acc, se[wl][j], Xu, lane);
        } else {
            for (int j = 0; j < take; ++j) gather_fma(acc, se[wl][j], Xu, lane);
        }
        __syncwarp();
    }
    uint2 o = make_uint2(h2u(__floats2half2_rn(sigf(acc.x), sigf(acc.y))),
                         h2u(__floats2half2_rn(sigf(acc.z), sigf(acc.w))));
    reinterpret_cast<uint2*>(out)[(size_t)w * 32 + lane] = o;
}

// partial (fp32) = incCSR @ X   (no sigmoid; overlapped off the critical tail)
__global__ __launch_bounds__(256) void spmm_partial(const int* __restrict__ ptr,
                                                    const int2* __restrict__ e,
                                                    const __half* __restrict__ X,
                                                    float4* __restrict__ out, int nrows)
{
    __shared__ int2 se[8][32];
    int w    = (blockIdx.x * blockDim.x + threadIdx.x) >> 5;
    int lane = threadIdx.x & 31;
    int wl   = threadIdx.x >> 5;
    if (w >= nrows) return;
    const uint2* Xu = reinterpret_cast<const uint2*>(X);
    int start = ptr[w], end = ptr[w + 1];
    float4 acc = make_float4(0.f, 0.f, 0.f, 0.f);
    for (int i = start; i < end; i += 32) {
        int take = min(32, end - i);
        if (lane < take) se[wl][lane] = e[i + lane];
        __syncwarp();
        for (int j = 0; j < take; ++j) gather_fma(acc, se[wl][j], Xu, lane);
        __syncwarp();
    }
    out[(size_t)w * 32 + lane] = acc;
}

// out (fp32) = sigmoid(adjCSR @ XA + partial)   (tail kernel: adj gather only)
__global__ __launch_bounds__(256) void spmm_final(const int* __restrict__ ptrA,
                                                  const int2* __restrict__ e,
                                                  const __half* __restrict__ XA,
                                                  const float4* __restrict__ partial,
                                                  float4* __restrict__ out, int nrows)
{
    __shared__ int2 se[8][32];
    int w    = (blockIdx.x * blockDim.x + threadIdx.x) >> 5;
    int lane = threadIdx.x & 31;
    int wl   = threadIdx.x >> 5;
    if (w >= nrows) return;
    const uint2* Xu = reinterpret_cast<const uint2*>(XA);
    int start = ptrA[w], end = ptrA[w + 1];
    float4 acc = partial[(size_t)w * 32 + lane];
    for (int i = start; i < end; i += 32) {
        int take = min(32, end - i);
        if (lane < take) se[wl][lane] = e[i + lane];
        __syncwarp();
        if (take == 32) {
            #pragma unroll 8
            for (int j = 0; j < 32; ++j) gather_fma(acc, se[wl][j], Xu, lane);
        } else {
            for (int j = 0; j < take; ++j) gather_fma(acc, se[wl][j], Xu, lane);
        }
        __syncwarp();
    }
    acc.x = sigf(acc.x); acc.y = sigf(acc.y); acc.z = sigf(acc.z); acc.w = sigf(acc.w);
    out[(size_t)w * 32 + lane] = acc;
}

// ---------------- host ----------------
extern "C" void kernel_launch(void* const* d_in, const int* in_sizes, int n_in,
                              void* d_out, int out_size)
{
    const float* x        = (const float*)d_in[0];
    const float* W1_00    = (const float*)d_in[1];
    const float* W1_01    = (const float*)d_in[2];
    const float* W2_00    = (const float*)d_in[3];
    const float* W2_10    = (const float*)d_in[4];
    const int*   adj_rows = (const int*)  d_in[5];
    const int*   adj_cols = (const int*)  d_in[6];
    const float* adj_vals = (const float*)d_in[7];
    const int*   inc_rows = (const int*)  d_in[8];
    const int*   inc_cols = (const int*)  d_in[9];
    const float* inc_vals = (const float*)d_in[10];
    const int adj_nnz = in_sizes[5];
    const int inc_nnz = in_sizes[8];
    const int nodes   = NNODES;
    const int edges   = NEDGES;
    const int nnz_tot = adj_nnz + 2 * inc_nnz;

    __half *hx, *h1, *h2, *h4, *hY, *hB, *hC, *hW;
    float *pf;
    int *cnt, *ptr, *work, *sums;
    int2 *eAll;
    cudaGetSymbolAddress((void**)&hx, g_hx);
    cudaGetSymbolAddress((void**)&h1, g_h1);
    cudaGetSymbolAddress((void**)&h2, g_h2);
    cudaGetSymbolAddress((void**)&h4, g_h4);
    cudaGetSymbolAddress((void**)&hY, g_hY);
    cudaGetSymbolAddress((void**)&hB, g_hB);
    cudaGetSymbolAddress((void**)&hC, g_hC);
    cudaGetSymbolAddress((void**)&hW, g_hW);
    cudaGetSymbolAddress((void**)&pf, g_pf);
    cudaGetSymbolAddress((void**)&cnt,  g_cnt);
    cudaGetSymbolAddress((void**)&ptr,  g_ptr);
    cudaGetSymbolAddress((void**)&work, g_work);
    cudaGetSymbolAddress((void**)&sums, g_sums);
    cudaGetSymbolAddress((void**)&eAll, g_e);

    __half* hW0 = hW;
    __half* hW1 = hW + CDIM * CDIM;
    __half* hW2 = hW + 2 * CDIM * CDIM;
    __half* hW3 = hW + 3 * CDIM * CDIM;

    static cudaStream_t s1 = nullptr;
    static cudaEvent_t evFork = nullptr, evG1 = nullptr, evBuild = nullptr, evPart = nullptr;
    if (!s1) {
        cudaStreamCreateWithFlags(&s1, cudaStreamNonBlocking);
        cudaEventCreateWithFlags(&evFork,  cudaEventDisableTiming);
        cudaEventCreateWithFlags(&evG1,    cudaEventDisableTiming);
        cudaEventCreateWithFlags(&evBuild, cudaEventDisableTiming);
        cudaEventCreateWithFlags(&evPart,  cudaEventDisableTiming);
        cudaFuncSetAttribute(gemm_tc, cudaFuncAttributeMaxDynamicSharedMemorySize,
                             128 * LDH * 2 * 2);
    }
    const int SMEM = 128 * LDH * 2 * 2;

    // ---- fork ----
    cudaEventRecord(evFork, 0);
    cudaStreamWaitEvent(s1, evFork, 0);

    // ---- stream s1: converts + level-1 GEMMs ----
    int xN4 = nodes * CDIM / 4;
    f2h_kernel<<<(xN4 + 255) / 256, 256, 0, s1>>>((const float4*)x, (uint2*)hx, xN4);
    f2h_w4<<<(4 * 4096 + 255) / 256, 256, 0, s1>>>((const float4*)W1_00, (const float4*)W1_01,
                                                   (const float4*)W2_00, (const float4*)W2_10,
                                                   (uint2*)hW0);
    gemm_tc<<<(nodes + 127) / 128, 256, SMEM, s1>>>(hx, hW0, h1, nodes);
    cudaEventRecord(evG1, s1);
    gemm_tc<<<(nodes + 127) / 128, 256, SMEM, s1>>>(hx, hW1, h2, nodes);

    // ---- stream 0: unified CSR build ----
    cudaMemsetAsync(cnt, 0, (size_t)NTOT * sizeof(int), 0);
    {
        int mx = max(adj_nnz, inc_nnz);
        hist_all<<<(mx + 255) / 256, 256>>>(adj_rows, adj_nnz, inc_rows, inc_cols, inc_nnz, cnt);
        int nB = (NTOT + 4095) / 4096;
        scan_chunk<<<nB, 1024>>>(cnt, ptr, sums, NTOT);
        scan_sums<<<1, 128>>>(sums, nB);
        add_base_work<<<(NTOT + 255) / 256, 256>>>(ptr, work, sums, NTOT, nnz_tot);
        scatter_all<<<(mx + 255) / 256, 256>>>(adj_rows, adj_cols, adj_vals, adj_nnz,
                                               inc_rows, inc_cols, inc_vals, inc_nnz,
                                               work, eAll);
    }
    cudaEventRecord(evBuild, 0);

    // ---- stream 0: node branch (S1 -> G3) ----
    cudaStreamWaitEvent(0, evG1, 0);
    spmm_h<<<(nodes + 7) / 8, 256>>>(ptr, eAll, h1, hB, nodes);                 // adj rows
    gemm_tc<<<(nodes + 127) / 128, 256, SMEM>>>(hB, hW2, hY, nodes);

    // ---- stream s1: edge branch (S2 -> G4 -> partial) ----
    cudaStreamWaitEvent(s1, evBuild, 0);
    spmm_h<<<(edges + 7) / 8, 256, 0, s1>>>(ptr + nodes, eAll, h2, hC, edges);  // incT rows
    gemm_tc<<<(edges + 127) / 128, 256, SMEM, s1>>>(hC, hW3, h4, edges);
    spmm_partial<<<(nodes + 7) / 8, 256, 0, s1>>>(ptr + nodes + edges, eAll, h4,
                                                  (float4*)pf, nodes);          // inc rows
    cudaEventRecord(evPart, s1);

    // ---- join + tail (adj gather only) ----
    cudaStreamWaitEvent(0, evPart, 0);
    spmm_final<<<(nodes + 7) / 8, 256>>>(ptr, eAll, hY, (const float4*)pf,
                                         (float4*)d_out, nodes);
}